// round 1
// baseline (speedup 1.0000x reference)
#include <cuda_runtime.h>
#include <math.h>

#define BATCH 512
#define LSEQ  100
#define NINPUT 3
#define HDIM  256
#define G3    768
#define DSH   10
#define WINW  5
#define MSEQ  95          // LSEQ - WINW
#define TB    8           // batch samples per recurrent block

#define BL    (BATCH*LSEQ)      // 51200
#define BM95  (BATCH*MSEQ)      // 48640

// ---------------- scratch (static device memory; no allocations) ----------
__device__ float  g_xw0 [2*BL*G3];          // layer-0 gate inputs, per GRU
__device__ float  g_h1  [2*BL*HDIM];        // layer-0 outputs
__device__ float  g_out [2*BL*HDIM];        // layer-1 outputs (out1/out2)
__device__ float  g_q   [2*BL];
__device__ float  g_e   [2*BL];
__device__ float  g_cat [2*BM95*2*HDIM];    // [c, out_shift] concat for FC
__device__ float  g_fused[2*BM95*HDIM];     // FC output
__device__ float4 g_wT4 [6*64*G3];          // transposed weights, float4 over k
// wT4 slots: 0=r1_Whh0 1=r2_Whh0 2=r1_Whh1 3=r2_Whh1 4=r1_Wih1 5=r2_Wih1

__device__ __forceinline__ float sigf(float x) { return 1.f / (1.f + __expf(-x)); }

// ---------------- weight transpose: W[g][k] -> wT4[k/4][g] ----------------
__global__ void k_prep(const float* __restrict__ w0, const float* __restrict__ w1,
                       const float* __restrict__ w2, const float* __restrict__ w3,
                       const float* __restrict__ w4, const float* __restrict__ w5)
{
    int idx = blockIdx.x * blockDim.x + threadIdx.x;
    if (idx >= 6 * 64 * G3) return;
    int g  = idx % G3;
    int k4 = (idx / G3) % 64;
    int m  = idx / (G3 * 64);
    const float* W = (m == 0) ? w0 : (m == 1) ? w1 : (m == 2) ? w2
                   : (m == 3) ? w3 : (m == 4) ? w4 : w5;
    const float* p = W + g * HDIM + 4 * k4;
    g_wT4[idx] = make_float4(p[0], p[1], p[2], p[3]);
}

// ---------------- layer-0 gate inputs: xw0 = x @ Wih0.T + bih0 ------------
__global__ void k_xw0(const float* __restrict__ x,
                      const float* __restrict__ W0, const float* __restrict__ W1,
                      const float* __restrict__ b0, const float* __restrict__ b1)
{
    int idx = blockIdx.x * blockDim.x + threadIdx.x;
    if (idx >= 2 * BL * G3) return;
    int g  = idx % G3;
    int bl = (idx / G3) % BL;
    int r  = idx / (G3 * BL);
    const float* W = r ? W1 : W0;
    const float* bb = r ? b1 : b0;
    const float* xp = x + bl * NINPUT;
    g_xw0[idx] = bb[g] + xp[0]*W[g*3+0] + xp[1]*W[g*3+1] + xp[2]*W[g*3+2];
}

// ---------------- GRU layer 0 (recurrent, both GRUs via blockIdx.y) -------
__global__ void __launch_bounds__(256, 1)
k_rec_l0(const float* __restrict__ bhh_0, const float* __restrict__ bhh_1)
{
    int r  = blockIdx.y;
    int j  = threadIdx.x;                 // gate index 0..255
    int b0 = blockIdx.x * TB;
    const float*  bhh = r ? bhh_1 : bhh_0;
    const float4* W   = g_wT4 + (size_t)r * (64 * G3);
    const float*  xw  = g_xw0 + (size_t)r * BL * G3;
    float*        h1  = g_h1  + (size_t)r * BL * HDIM;

    __shared__ float hs[TB][HDIM];
#pragma unroll
    for (int b = 0; b < TB; b++) hs[b][j] = 0.f;
    float bhr = bhh[j], bhz = bhh[j + HDIM], bhn = bhh[j + 2*HDIM];
    __syncthreads();

    for (int t = 0; t < LSEQ; t++) {
        float ar[TB], az[TB], an[TB];
#pragma unroll
        for (int b = 0; b < TB; b++) { ar[b] = 0.f; az[b] = 0.f; an[b] = 0.f; }

#pragma unroll 4
        for (int k4 = 0; k4 < 64; k4++) {
            float4 w0 = W[k4*G3 + j];
            float4 w1 = W[k4*G3 + HDIM + j];
            float4 w2 = W[k4*G3 + 2*HDIM + j];
#pragma unroll
            for (int b = 0; b < TB; b++) {
                float4 h4 = *(const float4*)&hs[b][k4*4];
                ar[b] += w0.x*h4.x + w0.y*h4.y + w0.z*h4.z + w0.w*h4.w;
                az[b] += w1.x*h4.x + w1.y*h4.y + w1.z*h4.z + w1.w*h4.w;
                an[b] += w2.x*h4.x + w2.y*h4.y + w2.z*h4.z + w2.w*h4.w;
            }
        }
        __syncthreads();
#pragma unroll
        for (int b = 0; b < TB; b++) {
            size_t base = ((size_t)(b0 + b) * LSEQ + t) * G3;
            float rg = sigf(xw[base + j]          + ar[b] + bhr);
            float zg = sigf(xw[base + HDIM + j]   + az[b] + bhz);
            float ng = tanhf(xw[base + 2*HDIM + j] + rg * (an[b] + bhn));
            float hn = (1.f - zg) * ng + zg * hs[b][j];
            hs[b][j] = hn;
            h1[((size_t)(b0 + b) * LSEQ + t) * HDIM + j] = hn;
        }
        __syncthreads();
    }
}

// ---------------- GRU layer 1 (recurrent + folded input projection) -------
__global__ void __launch_bounds__(256, 1)
k_rec_l1(const float* __restrict__ bih_0, const float* __restrict__ bih_1,
         const float* __restrict__ bhh_0, const float* __restrict__ bhh_1)
{
    int r  = blockIdx.y;
    int j  = threadIdx.x;
    int b0 = blockIdx.x * TB;
    const float*  bih = r ? bih_1 : bih_0;
    const float*  bhh = r ? bhh_1 : bhh_0;
    const float4* Wh  = g_wT4 + (size_t)(2 + r) * (64 * G3);
    const float4* Wx  = g_wT4 + (size_t)(4 + r) * (64 * G3);
    const float*  h1  = g_h1  + (size_t)r * BL * HDIM;
    float*        out = g_out + (size_t)r * BL * HDIM;

    __shared__ float hs[TB][HDIM];
    __shared__ float xs[TB][HDIM];
#pragma unroll
    for (int b = 0; b < TB; b++) hs[b][j] = 0.f;
    float bxr = bih[j], bxz = bih[j + HDIM], bxn = bih[j + 2*HDIM];
    float bhr = bhh[j], bhz = bhh[j + HDIM], bhn = bhh[j + 2*HDIM];
    __syncthreads();

    for (int t = 0; t < LSEQ; t++) {
        // stage this step's layer-0 output
#pragma unroll
        for (int b = 0; b < TB; b++)
            xs[b][j] = h1[((size_t)(b0 + b) * LSEQ + t) * HDIM + j];
        __syncthreads();

        float xr[TB], xz[TB], xn[TB], ar[TB], az[TB], an[TB];
#pragma unroll
        for (int b = 0; b < TB; b++) {
            xr[b]=0.f; xz[b]=0.f; xn[b]=0.f; ar[b]=0.f; az[b]=0.f; an[b]=0.f;
        }
#pragma unroll 2
        for (int k4 = 0; k4 < 64; k4++) {
            float4 u0 = Wx[k4*G3 + j];
            float4 u1 = Wx[k4*G3 + HDIM + j];
            float4 u2 = Wx[k4*G3 + 2*HDIM + j];
            float4 w0 = Wh[k4*G3 + j];
            float4 w1 = Wh[k4*G3 + HDIM + j];
            float4 w2 = Wh[k4*G3 + 2*HDIM + j];
#pragma unroll
            for (int b = 0; b < TB; b++) {
                float4 x4 = *(const float4*)&xs[b][k4*4];
                float4 h4 = *(const float4*)&hs[b][k4*4];
                xr[b] += u0.x*x4.x + u0.y*x4.y + u0.z*x4.z + u0.w*x4.w;
                xz[b] += u1.x*x4.x + u1.y*x4.y + u1.z*x4.z + u1.w*x4.w;
                xn[b] += u2.x*x4.x + u2.y*x4.y + u2.z*x4.z + u2.w*x4.w;
                ar[b] += w0.x*h4.x + w0.y*h4.y + w0.z*h4.z + w0.w*h4.w;
                az[b] += w1.x*h4.x + w1.y*h4.y + w1.z*h4.z + w1.w*h4.w;
                an[b] += w2.x*h4.x + w2.y*h4.y + w2.z*h4.z + w2.w*h4.w;
            }
        }
        __syncthreads();
#pragma unroll
        for (int b = 0; b < TB; b++) {
            float rg = sigf(xr[b] + bxr + ar[b] + bhr);
            float zg = sigf(xz[b] + bxz + az[b] + bhz);
            float ng = tanhf(xn[b] + bxn + rg * (an[b] + bhn));
            float hn = (1.f - zg) * ng + zg * hs[b][j];
            hs[b][j] = hn;
            out[((size_t)(b0 + b) * LSEQ + t) * HDIM + j] = hn;
        }
        __syncthreads();
    }
}

// ---------------- q = out@aw[:H], e = out@aw[H:] (warp per (b,l)) ----------
__global__ void k_qe(const float* __restrict__ attn_w)
{
    int r    = blockIdx.y;
    int w    = blockIdx.x * 8 + (threadIdx.x >> 5);  // 0..51199
    int lane = threadIdx.x & 31;
    const float* o = g_out + ((size_t)r * BL + w) * HDIM;
    float q = 0.f, e = 0.f;
#pragma unroll
    for (int h = lane * 8; h < lane * 8 + 8; h += 4) {
        float4 ov = *(const float4*)&o[h];
        float4 a1 = *(const float4*)&attn_w[h];
        float4 a2 = *(const float4*)&attn_w[HDIM + h];
        q += ov.x*a1.x + ov.y*a1.y + ov.z*a1.z + ov.w*a1.w;
        e += ov.x*a2.x + ov.y*a2.y + ov.z*a2.z + ov.w*a2.w;
    }
#pragma unroll
    for (int off = 16; off; off >>= 1) {
        q += __shfl_down_sync(0xffffffffu, q, off);
        e += __shfl_down_sync(0xffffffffu, e, off);
    }
    if (lane == 0) { g_q[r * BL + w] = q; g_e[r * BL + w] = e; }
}

// ---------------- windowed attention + concat for FC ----------------------
__global__ void k_attn()
{
    int r    = blockIdx.y;
    int bl95 = blockIdx.x;                 // 0..48639
    int b    = bl95 / MSEQ, l = bl95 % MSEQ;
    int h    = threadIdx.x;

    const float* qrow = g_q + r * BL + b * LSEQ;
    const float* erow = g_e + r * BL + b * LSEQ;
    float qv = qrow[l + WINW];
    float s[WINW];
    float mx = -1e30f;
#pragma unroll
    for (int k = 0; k < WINW; k++) { s[k] = qv + erow[l + k]; mx = fmaxf(mx, s[k]); }
    float sum = 0.f;
#pragma unroll
    for (int k = 0; k < WINW; k++) { s[k] = __expf(s[k] - mx); sum += s[k]; }
    float inv = 1.f / sum;

    const float* o = g_out + ((size_t)r * BL + b * LSEQ + l) * HDIM;
    float c = 0.f;
#pragma unroll
    for (int k = 0; k < WINW; k++) c += s[k] * inv * o[k * HDIM + h];

    size_t m = (size_t)r * BM95 + bl95;
    g_cat[m * (2*HDIM) + h]        = c;
    g_cat[m * (2*HDIM) + HDIM + h] = o[WINW * HDIM + h];
}

// ---------------- FC GEMM: [97280,512] x fc_W.T -> [97280,256] -------------
__global__ void __launch_bounds__(256)
k_fc(const float* __restrict__ Bw, const float* __restrict__ bias)
{
    __shared__ float As[16][64];
    __shared__ float Bs[16][64];
    int bm = blockIdx.y * 64;
    int bn = blockIdx.x * 64;
    int tid = threadIdx.x;
    int tm = (tid / 16) * 4;
    int tn = (tid % 16) * 4;
    int lr = tid / 4;          // tile row for loads
    int lk = (tid % 4) * 4;    // k offset for loads

    float acc[4][4];
#pragma unroll
    for (int i = 0; i < 4; i++)
#pragma unroll
        for (int jj = 0; jj < 4; jj++) acc[i][jj] = 0.f;

    for (int k0 = 0; k0 < 2*HDIM; k0 += 16) {
        float4 a4 = *(const float4*)&g_cat[(size_t)(bm + lr) * (2*HDIM) + k0 + lk];
        float4 b4 = *(const float4*)&Bw  [(size_t)(bn + lr) * (2*HDIM) + k0 + lk];
        As[lk+0][lr] = a4.x; As[lk+1][lr] = a4.y; As[lk+2][lr] = a4.z; As[lk+3][lr] = a4.w;
        Bs[lk+0][lr] = b4.x; Bs[lk+1][lr] = b4.y; Bs[lk+2][lr] = b4.z; Bs[lk+3][lr] = b4.w;
        __syncthreads();
#pragma unroll
        for (int k = 0; k < 16; k++) {
            float4 av = *(const float4*)&As[k][tm];
            float4 bv = *(const float4*)&Bs[k][tn];
            acc[0][0] += av.x*bv.x; acc[0][1] += av.x*bv.y; acc[0][2] += av.x*bv.z; acc[0][3] += av.x*bv.w;
            acc[1][0] += av.y*bv.x; acc[1][1] += av.y*bv.y; acc[1][2] += av.y*bv.z; acc[1][3] += av.y*bv.w;
            acc[2][0] += av.z*bv.x; acc[2][1] += av.z*bv.y; acc[2][2] += av.z*bv.z; acc[2][3] += av.z*bv.w;
            acc[3][0] += av.w*bv.x; acc[3][1] += av.w*bv.y; acc[3][2] += av.w*bv.z; acc[3][3] += av.w*bv.w;
        }
        __syncthreads();
    }
    float b0v = bias[bn+tn+0], b1v = bias[bn+tn+1], b2v = bias[bn+tn+2], b3v = bias[bn+tn+3];
#pragma unroll
    for (int i = 0; i < 4; i++) {
        float4 cv = make_float4(acc[i][0]+b0v, acc[i][1]+b1v, acc[i][2]+b2v, acc[i][3]+b3v);
        *(float4*)&g_fused[(size_t)(bm + tm + i) * HDIM + bn + tn] = cv;
    }
}

// ---------------- final head: concat(rnn1[b,l], rnn2[b,min(l+D,99)]) ------
__global__ void k_final(const float* __restrict__ outW, const float* __restrict__ outb,
                        float* __restrict__ out)
{
    int w    = blockIdx.x * 8 + (threadIdx.x >> 5);  // 0..51199
    int lane = threadIdx.x & 31;
    int b = w / LSEQ, l = w % LSEQ;

    const float* A1 = (l < WINW)
        ? (g_out   + ((size_t)(b * LSEQ + l)) * HDIM)
        : (g_fused + ((size_t)(b * MSEQ + l - WINW)) * HDIM);
    int lidx = min(l + DSH, LSEQ - 1);
    const float* A2 = (lidx < WINW)
        ? (g_out   + ((size_t)BL + b * LSEQ + lidx) * HDIM)
        : (g_fused + ((size_t)BM95 + b * MSEQ + lidx - WINW) * HDIM);

    float acc = 0.f;
#pragma unroll
    for (int h = lane * 8; h < lane * 8 + 8; h += 4) {
        float4 a  = *(const float4*)&A1[h];
        float4 w1 = *(const float4*)&outW[h];
        acc += a.x*w1.x + a.y*w1.y + a.z*w1.z + a.w*w1.w;
        float4 a2 = *(const float4*)&A2[h];
        float4 w2 = *(const float4*)&outW[HDIM + h];
        acc += a2.x*w2.x + a2.y*w2.y + a2.z*w2.z + a2.w*w2.w;
    }
#pragma unroll
    for (int off = 16; off; off >>= 1)
        acc += __shfl_down_sync(0xffffffffu, acc, off);
    if (lane == 0) out[w] = 1.f / (1.f + __expf(-(acc + outb[0])));
}

// ---------------------------------------------------------------------------
extern "C" void kernel_launch(void* const* d_in, const int* in_sizes, int n_in,
                              void* d_out, int out_size)
{
    const float* received = (const float*)d_in[0];
    const float* r1_Wih0  = (const float*)d_in[1];
    const float* r1_Whh0  = (const float*)d_in[2];
    const float* r1_bih0  = (const float*)d_in[3];
    const float* r1_bhh0  = (const float*)d_in[4];
    const float* r1_Wih1  = (const float*)d_in[5];
    const float* r1_Whh1  = (const float*)d_in[6];
    const float* r1_bih1  = (const float*)d_in[7];
    const float* r1_bhh1  = (const float*)d_in[8];
    const float* r2_Wih0  = (const float*)d_in[9];
    const float* r2_Whh0  = (const float*)d_in[10];
    const float* r2_bih0  = (const float*)d_in[11];
    const float* r2_bhh0  = (const float*)d_in[12];
    const float* r2_Wih1  = (const float*)d_in[13];
    const float* r2_Whh1  = (const float*)d_in[14];
    const float* r2_bih1  = (const float*)d_in[15];
    const float* r2_bhh1  = (const float*)d_in[16];
    const float* attn_w   = (const float*)d_in[17];
    const float* fc_W     = (const float*)d_in[18];
    const float* fc_b     = (const float*)d_in[19];
    const float* out_W    = (const float*)d_in[20];
    const float* out_b    = (const float*)d_in[21];
    float* out = (float*)d_out;

    // 1. transpose the six 768x256 weight matrices into float4-over-k layout
    k_prep<<<(6*64*G3 + 255)/256, 256>>>(r1_Whh0, r2_Whh0, r1_Whh1, r2_Whh1,
                                         r1_Wih1, r2_Wih1);
    // 2. layer-0 gate inputs for both GRUs
    k_xw0<<<(2*BL*G3 + 255)/256, 256>>>(received, r1_Wih0, r2_Wih0, r1_bih0, r2_bih0);
    // 3. layer-0 recurrence (both GRUs concurrent via grid.y)
    k_rec_l0<<<dim3(BATCH/TB, 2), 256>>>(r1_bhh0, r2_bhh0);
    // 4. layer-1 recurrence with folded input projection
    k_rec_l1<<<dim3(BATCH/TB, 2), 256>>>(r1_bih1, r2_bih1, r1_bhh1, r2_bhh1);
    // 5. attention scalars q,e
    k_qe<<<dim3(BL/8, 2), 256>>>(attn_w);
    // 6. windowed softmax attention + concat
    k_attn<<<dim3(BM95, 2), 256>>>();
    // 7. FC over both branches stacked
    k_fc<<<dim3(HDIM/64, (2*BM95)/64), 256>>>(fc_W, fc_b);
    // 8. final projection + sigmoid
    k_final<<<BL/8, 256>>>(out_W, out_b, out);
}

// round 2
// speedup vs baseline: 1.0215x; 1.0215x over previous
#include <cuda_runtime.h>
#include <math.h>

#define BATCH 512
#define LSEQ  100
#define NINPUT 3
#define HDIM  256
#define G3    768
#define DSH   10
#define WINW  5
#define MSEQ  95          // LSEQ - WINW
#define TB    8           // batch samples per recurrent block

#define BL    (BATCH*LSEQ)      // 51200
#define BM95  (BATCH*MSEQ)      // 48640

typedef unsigned long long u64;

// ---------------- scratch (static device memory; no allocations) ----------
__device__ float  g_xw0 [2*BL*G3];          // layer-0 gate inputs, per GRU
__device__ float  g_xw1 [2*BL*G3];          // layer-1 gate inputs, per GRU
__device__ float  g_h1  [2*BL*HDIM];        // layer-0 outputs
__device__ float  g_out [2*BL*HDIM];        // layer-1 outputs (out1/out2)
__device__ float  g_q   [2*BL];
__device__ float  g_e   [2*BL];
__device__ float  g_cat [2*BM95*2*HDIM];    // [c, out_shift] concat for FC
__device__ float  g_fused[2*BM95*HDIM];     // FC output
__device__ float4 g_wT4 [4*64*G3];          // transposed Whh, float4 over k
// wT4 slots: 0=r1_Whh0 1=r2_Whh0 2=r1_Whh1 3=r2_Whh1

__device__ __forceinline__ float sigf(float x) { return 1.f / (1.f + __expf(-x)); }

// packed dual-fp32 FMA: acc.{lo,hi} += a.{lo,hi} * b.{lo,hi}
__device__ __forceinline__ void fma2(u64& acc, u64 a, u64 b) {
    asm("fma.rn.f32x2 %0, %1, %2, %0;" : "+l"(acc) : "l"(a), "l"(b));
}
__device__ __forceinline__ u64 splat2(float x) {
    u64 r; asm("mov.b64 %0, {%1, %1};" : "=l"(r) : "f"(x)); return r;
}
__device__ __forceinline__ float sum2(u64 v) {
    float lo, hi; asm("mov.b64 {%0, %1}, %2;" : "=f"(lo), "=f"(hi) : "l"(v));
    return lo + hi;
}

// ---------------- weight transpose: W[g][k] -> wT4[k/4][g] ----------------
__global__ void k_prep(const float* __restrict__ w0, const float* __restrict__ w1,
                       const float* __restrict__ w2, const float* __restrict__ w3)
{
    int idx = blockIdx.x * blockDim.x + threadIdx.x;
    if (idx >= 4 * 64 * G3) return;
    int g  = idx % G3;
    int k4 = (idx / G3) % 64;
    int m  = idx / (G3 * 64);
    const float* W = (m == 0) ? w0 : (m == 1) ? w1 : (m == 2) ? w2 : w3;
    const float* p = W + g * HDIM + 4 * k4;
    g_wT4[idx] = make_float4(p[0], p[1], p[2], p[3]);
}

// ---------------- layer-0 gate inputs: xw0 = x @ Wih0.T + bih0 ------------
__global__ void k_xw0(const float* __restrict__ x,
                      const float* __restrict__ W0, const float* __restrict__ W1,
                      const float* __restrict__ b0, const float* __restrict__ b1)
{
    int idx = blockIdx.x * blockDim.x + threadIdx.x;
    if (idx >= 2 * BL * G3) return;
    int g  = idx % G3;
    int bl = (idx / G3) % BL;
    int r  = idx / (G3 * BL);
    const float* W = r ? W1 : W0;
    const float* bb = r ? b1 : b0;
    const float* xp = x + bl * NINPUT;
    g_xw0[idx] = bb[g] + xp[0]*W[g*3+0] + xp[1]*W[g*3+1] + xp[2]*W[g*3+2];
}

// ---------------- GRU recurrence (shared by layer 0 and layer 1) ----------
// xw_base: precomputed gate inputs (bias folded). wslot selects Whh set.
__global__ void __launch_bounds__(256, 1)
k_rec(const float* __restrict__ xw_base, int wslot,
      const float* __restrict__ bhh_0, const float* __restrict__ bhh_1,
      float* __restrict__ hout_base)
{
    int r  = blockIdx.y;
    int j  = threadIdx.x;                 // gate/hidden index 0..255
    int b0 = blockIdx.x * TB;
    const float*  bhh  = r ? bhh_1 : bhh_0;
    const float4* W    = g_wT4 + (size_t)(wslot + r) * (64 * G3);
    const float*  xw   = xw_base   + (size_t)r * BL * G3;
    float*        hout = hout_base + (size_t)r * BL * HDIM;

    __shared__ __align__(16) float hs[TB][HDIM];
#pragma unroll
    for (int b = 0; b < TB; b++) hs[b][j] = 0.f;
    float bhr = bhh[j], bhz = bhh[j + HDIM], bhn = bhh[j + 2*HDIM];
    __syncthreads();

    for (int t = 0; t < LSEQ; t++) {
        u64 ar[TB], az[TB], an[TB];
#pragma unroll
        for (int b = 0; b < TB; b++) { ar[b] = 0ull; az[b] = 0ull; an[b] = 0ull; }

#pragma unroll 4
        for (int k4 = 0; k4 < 64; k4++) {
            ulonglong2 w0 = *(const ulonglong2*)&W[k4*G3 + j];
            ulonglong2 w1 = *(const ulonglong2*)&W[k4*G3 + HDIM + j];
            ulonglong2 w2 = *(const ulonglong2*)&W[k4*G3 + 2*HDIM + j];
#pragma unroll
            for (int b = 0; b < TB; b++) {
                ulonglong2 h2 = *(const ulonglong2*)&hs[b][k4*4];
                fma2(ar[b], w0.x, h2.x); fma2(ar[b], w0.y, h2.y);
                fma2(az[b], w1.x, h2.x); fma2(az[b], w1.y, h2.y);
                fma2(an[b], w2.x, h2.x); fma2(an[b], w2.y, h2.y);
            }
        }
        __syncthreads();
#pragma unroll
        for (int b = 0; b < TB; b++) {
            size_t base = ((size_t)(b0 + b) * LSEQ + t) * G3;
            float rg = sigf(xw[base + j]           + sum2(ar[b]) + bhr);
            float zg = sigf(xw[base + HDIM + j]    + sum2(az[b]) + bhz);
            float ng = tanhf(xw[base + 2*HDIM + j] + rg * (sum2(an[b]) + bhn));
            float hn = (1.f - zg) * ng + zg * hs[b][j];
            hs[b][j] = hn;
            hout[((size_t)(b0 + b) * LSEQ + t) * HDIM + j] = hn;
        }
        __syncthreads();
    }
}

// ---------------- generic SGEMM: C[M,N] = A[M,K] @ B[N,K].T + bias --------
// 64x64 tile, kt=16, 256 threads, 4x4 per thread, f32x2 math.
// z dimension selects an (A,B,bias,C) set (used for the two GRUs).
__global__ void __launch_bounds__(256)
k_gemm(const float* __restrict__ A, size_t strideAz,
       const float* __restrict__ B0, const float* __restrict__ B1,
       const float* __restrict__ bias0, const float* __restrict__ bias1,
       float* __restrict__ C, size_t strideCz,
       int N, int K)
{
    int z = blockIdx.z;
    const float* Az   = A + (size_t)z * strideAz;
    const float* Bw   = z ? B1 : B0;
    const float* bias = z ? bias1 : bias0;
    float*       Cz   = C + (size_t)z * strideCz;

    __shared__ __align__(16) float As[16][64];
    __shared__ __align__(16) float Bs[16][64];
    int bm = blockIdx.y * 64;
    int bn = blockIdx.x * 64;
    int tid = threadIdx.x;
    int tm = (tid / 16) * 4;
    int tn = (tid % 16) * 4;
    int lr = tid / 4;          // tile row for loads
    int lk = (tid % 4) * 4;    // k offset for loads

    u64 acc2[2][4];            // M-pairs x N
#pragma unroll
    for (int i = 0; i < 2; i++)
#pragma unroll
        for (int jj = 0; jj < 4; jj++) acc2[i][jj] = 0ull;

    for (int k0 = 0; k0 < K; k0 += 16) {
        float4 a4 = *(const float4*)&Az[(size_t)(bm + lr) * K + k0 + lk];
        float4 b4 = *(const float4*)&Bw[(size_t)(bn + lr) * K + k0 + lk];
        As[lk+0][lr] = a4.x; As[lk+1][lr] = a4.y; As[lk+2][lr] = a4.z; As[lk+3][lr] = a4.w;
        Bs[lk+0][lr] = b4.x; Bs[lk+1][lr] = b4.y; Bs[lk+2][lr] = b4.z; Bs[lk+3][lr] = b4.w;
        __syncthreads();
#pragma unroll
        for (int k = 0; k < 16; k++) {
            ulonglong2 a2 = *(const ulonglong2*)&As[k][tm];   // pairs (m0,m1),(m2,m3)
            float4 bv = *(const float4*)&Bs[k][tn];
            u64 s0 = splat2(bv.x), s1 = splat2(bv.y), s2 = splat2(bv.z), s3 = splat2(bv.w);
            fma2(acc2[0][0], a2.x, s0); fma2(acc2[1][0], a2.y, s0);
            fma2(acc2[0][1], a2.x, s1); fma2(acc2[1][1], a2.y, s1);
            fma2(acc2[0][2], a2.x, s2); fma2(acc2[1][2], a2.y, s2);
            fma2(acc2[0][3], a2.x, s3); fma2(acc2[1][3], a2.y, s3);
        }
        __syncthreads();
    }
    float bv0 = bias[bn+tn+0], bv1 = bias[bn+tn+1], bv2 = bias[bn+tn+2], bv3 = bias[bn+tn+3];
#pragma unroll
    for (int p = 0; p < 2; p++) {
        float c00, c10, c01, c11, c02, c12, c03, c13;
        asm("mov.b64 {%0, %1}, %2;" : "=f"(c00), "=f"(c10) : "l"(acc2[p][0]));
        asm("mov.b64 {%0, %1}, %2;" : "=f"(c01), "=f"(c11) : "l"(acc2[p][1]));
        asm("mov.b64 {%0, %1}, %2;" : "=f"(c02), "=f"(c12) : "l"(acc2[p][2]));
        asm("mov.b64 {%0, %1}, %2;" : "=f"(c03), "=f"(c13) : "l"(acc2[p][3]));
        float4 r0 = make_float4(c00+bv0, c01+bv1, c02+bv2, c03+bv3);
        float4 r1 = make_float4(c10+bv0, c11+bv1, c12+bv2, c13+bv3);
        *(float4*)&Cz[(size_t)(bm + tm + 2*p + 0) * N + bn + tn] = r0;
        *(float4*)&Cz[(size_t)(bm + tm + 2*p + 1) * N + bn + tn] = r1;
    }
}

// ---------------- q = out@aw[:H], e = out@aw[H:] (warp per (b,l)) ----------
__global__ void k_qe(const float* __restrict__ attn_w)
{
    int r    = blockIdx.y;
    int w    = blockIdx.x * 8 + (threadIdx.x >> 5);  // 0..51199
    int lane = threadIdx.x & 31;
    const float* o = g_out + ((size_t)r * BL + w) * HDIM;
    float q = 0.f, e = 0.f;
#pragma unroll
    for (int h = lane * 8; h < lane * 8 + 8; h += 4) {
        float4 ov = *(const float4*)&o[h];
        float4 a1 = *(const float4*)&attn_w[h];
        float4 a2 = *(const float4*)&attn_w[HDIM + h];
        q += ov.x*a1.x + ov.y*a1.y + ov.z*a1.z + ov.w*a1.w;
        e += ov.x*a2.x + ov.y*a2.y + ov.z*a2.z + ov.w*a2.w;
    }
#pragma unroll
    for (int off = 16; off; off >>= 1) {
        q += __shfl_down_sync(0xffffffffu, q, off);
        e += __shfl_down_sync(0xffffffffu, e, off);
    }
    if (lane == 0) { g_q[r * BL + w] = q; g_e[r * BL + w] = e; }
}

// ---------------- windowed attention + concat for FC ----------------------
__global__ void k_attn()
{
    int r    = blockIdx.y;
    int bl95 = blockIdx.x;                 // 0..48639
    int b    = bl95 / MSEQ, l = bl95 % MSEQ;
    int h    = threadIdx.x;

    const float* qrow = g_q + r * BL + b * LSEQ;
    const float* erow = g_e + r * BL + b * LSEQ;
    float qv = qrow[l + WINW];
    float s[WINW];
    float mx = -1e30f;
#pragma unroll
    for (int k = 0; k < WINW; k++) { s[k] = qv + erow[l + k]; mx = fmaxf(mx, s[k]); }
    float sum = 0.f;
#pragma unroll
    for (int k = 0; k < WINW; k++) { s[k] = __expf(s[k] - mx); sum += s[k]; }
    float inv = 1.f / sum;

    const float* o = g_out + ((size_t)r * BL + b * LSEQ + l) * HDIM;
    float c = 0.f;
#pragma unroll
    for (int k = 0; k < WINW; k++) c += s[k] * inv * o[k * HDIM + h];

    size_t m = (size_t)r * BM95 + bl95;
    g_cat[m * (2*HDIM) + h]        = c;
    g_cat[m * (2*HDIM) + HDIM + h] = o[WINW * HDIM + h];
}

// ---------------- final head: concat(rnn1[b,l], rnn2[b,min(l+D,99)]) ------
__global__ void k_final(const float* __restrict__ outW, const float* __restrict__ outb,
                        float* __restrict__ out)
{
    int w    = blockIdx.x * 8 + (threadIdx.x >> 5);  // 0..51199
    int lane = threadIdx.x & 31;
    int b = w / LSEQ, l = w % LSEQ;

    const float* A1 = (l < WINW)
        ? (g_out   + ((size_t)(b * LSEQ + l)) * HDIM)
        : (g_fused + ((size_t)(b * MSEQ + l - WINW)) * HDIM);
    int lidx = min(l + DSH, LSEQ - 1);
    const float* A2 = (lidx < WINW)
        ? (g_out   + ((size_t)BL + b * LSEQ + lidx) * HDIM)
        : (g_fused + ((size_t)BM95 + b * MSEQ + lidx - WINW) * HDIM);

    float acc = 0.f;
#pragma unroll
    for (int h = lane * 8; h < lane * 8 + 8; h += 4) {
        float4 a  = *(const float4*)&A1[h];
        float4 w1 = *(const float4*)&outW[h];
        acc += a.x*w1.x + a.y*w1.y + a.z*w1.z + a.w*w1.w;
        float4 a2 = *(const float4*)&A2[h];
        float4 w2 = *(const float4*)&outW[HDIM + h];
        acc += a2.x*w2.x + a2.y*w2.y + a2.z*w2.z + a2.w*w2.w;
    }
#pragma unroll
    for (int off = 16; off; off >>= 1)
        acc += __shfl_down_sync(0xffffffffu, acc, off);
    if (lane == 0) out[w] = 1.f / (1.f + __expf(-(acc + outb[0])));
}

// ---------------------------------------------------------------------------
extern "C" void kernel_launch(void* const* d_in, const int* in_sizes, int n_in,
                              void* d_out, int out_size)
{
    const float* received = (const float*)d_in[0];
    const float* r1_Wih0  = (const float*)d_in[1];
    const float* r1_Whh0  = (const float*)d_in[2];
    const float* r1_bih0  = (const float*)d_in[3];
    const float* r1_bhh0  = (const float*)d_in[4];
    const float* r1_Wih1  = (const float*)d_in[5];
    const float* r1_Whh1  = (const float*)d_in[6];
    const float* r1_bih1  = (const float*)d_in[7];
    const float* r1_bhh1  = (const float*)d_in[8];
    const float* r2_Wih0  = (const float*)d_in[9];
    const float* r2_Whh0  = (const float*)d_in[10];
    const float* r2_bih0  = (const float*)d_in[11];
    const float* r2_bhh0  = (const float*)d_in[12];
    const float* r2_Wih1  = (const float*)d_in[13];
    const float* r2_Whh1  = (const float*)d_in[14];
    const float* r2_bih1  = (const float*)d_in[15];
    const float* r2_bhh1  = (const float*)d_in[16];
    const float* attn_w   = (const float*)d_in[17];
    const float* fc_W     = (const float*)d_in[18];
    const float* fc_b     = (const float*)d_in[19];
    const float* out_W    = (const float*)d_in[20];
    const float* out_b    = (const float*)d_in[21];
    float* out = (float*)d_out;

    float* d_xw0;   cudaGetSymbolAddress((void**)&d_xw0,   g_xw0);
    float* d_xw1;   cudaGetSymbolAddress((void**)&d_xw1,   g_xw1);
    float* d_h1;    cudaGetSymbolAddress((void**)&d_h1,    g_h1);
    float* d_gout;  cudaGetSymbolAddress((void**)&d_gout,  g_out);
    float* d_cat;   cudaGetSymbolAddress((void**)&d_cat,   g_cat);
    float* d_fused; cudaGetSymbolAddress((void**)&d_fused, g_fused);

    // 1. transpose the four 768x256 recurrent matrices into float4-over-k layout
    k_prep<<<(4*64*G3 + 255)/256, 256>>>(r1_Whh0, r2_Whh0, r1_Whh1, r2_Whh1);
    // 2. layer-0 gate inputs for both GRUs
    k_xw0<<<(2*BL*G3 + 255)/256, 256>>>(received, r1_Wih0, r2_Wih0, r1_bih0, r2_bih0);
    // 3. layer-0 recurrence (both GRUs concurrent via grid.y)
    k_rec<<<dim3(BATCH/TB, 2), 256>>>(d_xw0, 0, r1_bhh0, r2_bhh0, d_h1);
    // 4. layer-1 gate inputs: xw1 = h1 @ Wih1.T + bih1 (both GRUs via grid.z)
    k_gemm<<<dim3(G3/64, BL/64, 2), 256>>>(d_h1, (size_t)BL*HDIM,
                                           r1_Wih1, r2_Wih1, r1_bih1, r2_bih1,
                                           d_xw1, (size_t)BL*G3, G3, HDIM);
    // 5. layer-1 recurrence
    k_rec<<<dim3(BATCH/TB, 2), 256>>>(d_xw1, 2, r1_bhh1, r2_bhh1, d_gout);
    // 6. attention scalars q,e
    k_qe<<<dim3(BL/8, 2), 256>>>(attn_w);
    // 7. windowed softmax attention + concat
    k_attn<<<dim3(BM95, 2), 256>>>();
    // 8. FC over both branches stacked
    k_gemm<<<dim3(HDIM/64, (2*BM95)/64, 1), 256>>>(d_cat, 0,
                                                   fc_W, fc_W, fc_b, fc_b,
                                                   d_fused, 0, HDIM, 2*HDIM);
    // 9. final projection + sigmoid
    k_final<<<BL/8, 256>>>(out_W, out_b, out);
}

// round 3
// speedup vs baseline: 1.4174x; 1.3876x over previous
#include <cuda_runtime.h>
#include <math.h>

#define BATCH 512
#define LSEQ  100
#define NINPUT 3
#define HDIM  256
#define G3    768
#define DSH   10
#define WINW  5
#define MSEQ  95          // LSEQ - WINW
#define TB    8           // batch samples per recurrent block

#define BL    (BATCH*LSEQ)      // 51200
#define BM95  (BATCH*MSEQ)      // 48640

typedef unsigned long long u64;

// ---------------- scratch (static device memory; no allocations) ----------
__device__ float  g_xw1 [2*BL*G3];          // layer-1 gate inputs, per GRU
__device__ float  g_h1  [2*BL*HDIM];        // layer-0 outputs
__device__ float  g_out [2*BL*HDIM];        // layer-1 outputs (out1/out2)
__device__ float  g_q   [2*BL];
__device__ float  g_e   [2*BL];
__device__ float  g_cat [2*BM95*2*HDIM];    // [c, out_shift] concat for FC
__device__ float  g_fused[2*BM95*HDIM];     // FC output
__device__ float4 g_wT4 [4*64*G3];          // transposed Whh, float4 over k
// wT4 slots: 0=r1_Whh0 1=r2_Whh0 2=r1_Whh1 3=r2_Whh1

__device__ __forceinline__ float sigf(float x) { return 1.f / (1.f + __expf(-x)); }

// packed dual-fp32 FMA: acc.{lo,hi} += a.{lo,hi} * b.{lo,hi}
__device__ __forceinline__ void fma2(u64& acc, u64 a, u64 b) {
    asm("fma.rn.f32x2 %0, %1, %2, %0;" : "+l"(acc) : "l"(a), "l"(b));
}
__device__ __forceinline__ u64 splat2(float x) {
    u64 r; asm("mov.b64 %0, {%1, %1};" : "=l"(r) : "f"(x)); return r;
}
__device__ __forceinline__ float sum2(u64 v) {
    float lo, hi; asm("mov.b64 {%0, %1}, %2;" : "=f"(lo), "=f"(hi) : "l"(v));
    return lo + hi;
}

// ---------------- weight transpose: W[g][k] -> wT4[k/4][g] ----------------
__global__ void k_prep(const float* __restrict__ w0, const float* __restrict__ w1,
                       const float* __restrict__ w2, const float* __restrict__ w3)
{
    int idx = blockIdx.x * blockDim.x + threadIdx.x;
    if (idx >= 4 * 64 * G3) return;
    int g  = idx % G3;
    int k4 = (idx / G3) % 64;
    int m  = idx / (G3 * 64);
    const float* W = (m == 0) ? w0 : (m == 1) ? w1 : (m == 2) ? w2 : w3;
    const float* p = W + g * HDIM + 4 * k4;
    g_wT4[idx] = make_float4(p[0], p[1], p[2], p[3]);
}

// ---------------- GRU recurrence ------------------------------------------
// FUSE=1: layer 0 — input projection (NINPUT=3) fused, weights in registers.
// FUSE=0: layer 1 — reads precomputed gate inputs xw_base (bias folded).
template<int FUSE>
__global__ void __launch_bounds__(256, 1)
k_rec(const float* __restrict__ xw_base, const float* __restrict__ xin,
      const float* __restrict__ Wih_0, const float* __restrict__ Wih_1,
      const float* __restrict__ bih_0, const float* __restrict__ bih_1,
      int wslot,
      const float* __restrict__ bhh_0, const float* __restrict__ bhh_1,
      float* __restrict__ hout_base)
{
    int r  = blockIdx.y;
    int j  = threadIdx.x;                 // gate/hidden index 0..255
    int b0 = blockIdx.x * TB;
    const float*  bhh  = r ? bhh_1 : bhh_0;
    const float4* W    = g_wT4 + (size_t)(wslot + r) * (64 * G3);
    const float*  xw   = xw_base ? (xw_base + (size_t)r * BL * G3) : (const float*)0;
    float*        hout = hout_base + (size_t)r * BL * HDIM;

    // fused input-projection weights (layer 0 only)
    float wx[9], bx[3];
    if (FUSE) {
        const float* Wih = r ? Wih_1 : Wih_0;
        const float* bih = r ? bih_1 : bih_0;
#pragma unroll
        for (int g = 0; g < 3; g++) {
            wx[g*3+0] = Wih[(j + g*HDIM)*3 + 0];
            wx[g*3+1] = Wih[(j + g*HDIM)*3 + 1];
            wx[g*3+2] = Wih[(j + g*HDIM)*3 + 2];
            bx[g]     = bih[j + g*HDIM];
        }
    }

    __shared__ __align__(16) float hs[TB][HDIM];
    __shared__ float xs2[TB][4];
#pragma unroll
    for (int b = 0; b < TB; b++) hs[b][j] = 0.f;
    float bhr = bhh[j], bhz = bhh[j + HDIM], bhn = bhh[j + 2*HDIM];
    __syncthreads();

    for (int t = 0; t < LSEQ; t++) {
        if (FUSE && j < TB * 3) {
            int b = j / 3, c = j % 3;
            xs2[b][c] = xin[((size_t)(b0 + b) * LSEQ + t) * NINPUT + c];
        }
        u64 ar[TB], az[TB], an[TB];
#pragma unroll
        for (int b = 0; b < TB; b++) { ar[b] = 0ull; az[b] = 0ull; an[b] = 0ull; }

#pragma unroll 4
        for (int k4 = 0; k4 < 64; k4++) {
            ulonglong2 w0 = *(const ulonglong2*)&W[k4*G3 + j];
            ulonglong2 w1 = *(const ulonglong2*)&W[k4*G3 + HDIM + j];
            ulonglong2 w2 = *(const ulonglong2*)&W[k4*G3 + 2*HDIM + j];
#pragma unroll
            for (int b = 0; b < TB; b++) {
                ulonglong2 h2 = *(const ulonglong2*)&hs[b][k4*4];
                fma2(ar[b], w0.x, h2.x); fma2(ar[b], w0.y, h2.y);
                fma2(az[b], w1.x, h2.x); fma2(az[b], w1.y, h2.y);
                fma2(an[b], w2.x, h2.x); fma2(an[b], w2.y, h2.y);
            }
        }
        __syncthreads();
#pragma unroll
        for (int b = 0; b < TB; b++) {
            float gr, gz, gn;
            if (FUSE) {
                float x0 = xs2[b][0], x1 = xs2[b][1], x2 = xs2[b][2];
                gr = bx[0] + x0*wx[0] + x1*wx[1] + x2*wx[2];
                gz = bx[1] + x0*wx[3] + x1*wx[4] + x2*wx[5];
                gn = bx[2] + x0*wx[6] + x1*wx[7] + x2*wx[8];
            } else {
                size_t base = ((size_t)(b0 + b) * LSEQ + t) * G3;
                gr = xw[base + j];
                gz = xw[base + HDIM + j];
                gn = xw[base + 2*HDIM + j];
            }
            float rg = sigf(gr + sum2(ar[b]) + bhr);
            float zg = sigf(gz + sum2(az[b]) + bhz);
            float ng = tanhf(gn + rg * (sum2(an[b]) + bhn));
            float hn = (1.f - zg) * ng + zg * hs[b][j];
            hs[b][j] = hn;
            hout[((size_t)(b0 + b) * LSEQ + t) * HDIM + j] = hn;
        }
        __syncthreads();
    }
}

// ---------------- SGEMM: C[M,N] = A[M,K] @ B[N,K].T + bias ----------------
// 128x128 block tile, 256 threads, 8x8 per thread (f32x2), double-buffered.
// M % 128 == 0, N % 128 == 0, K % 8 == 0. z selects (A,B,bias,C) set.
__global__ void __launch_bounds__(256, 2)
k_gemm(const float* __restrict__ A, size_t strideAz,
       const float* __restrict__ B0, const float* __restrict__ B1,
       const float* __restrict__ bias0, const float* __restrict__ bias1,
       float* __restrict__ C, size_t strideCz,
       int N, int K)
{
    int z = blockIdx.z;
    const float* Az   = A + (size_t)z * strideAz;
    const float* Bw   = z ? B1 : B0;
    const float* bias = z ? bias1 : bias0;
    float*       Cz   = C + (size_t)z * strideCz;

    __shared__ __align__(16) float As[2][8][128];
    __shared__ __align__(16) float Bs[2][8][128];

    int bm = blockIdx.y * 128;
    int bn = blockIdx.x * 128;
    int tid = threadIdx.x;

    // load mapping: 128 rows x 8 k per tile; thread -> (row, 4-wide k chunk)
    int lrow = tid >> 1;
    int lk   = (tid & 1) * 4;
    // compute mapping: 16x16 thread grid, 8x8 micro-tile
    int tm = (tid >> 4) * 8;
    int tn = (tid & 15) * 8;

    u64 acc[4][8];   // 4 M-pairs x 8 N
#pragma unroll
    for (int p = 0; p < 4; p++)
#pragma unroll
        for (int n = 0; n < 8; n++) acc[p][n] = 0ull;

    const int KT = K >> 3;

    // preload tile 0
    float4 a4 = *(const float4*)&Az[(size_t)(bm + lrow) * K + lk];
    float4 b4 = *(const float4*)&Bw[(size_t)(bn + lrow) * K + lk];
    As[0][lk+0][lrow] = a4.x; As[0][lk+1][lrow] = a4.y;
    As[0][lk+2][lrow] = a4.z; As[0][lk+3][lrow] = a4.w;
    Bs[0][lk+0][lrow] = b4.x; Bs[0][lk+1][lrow] = b4.y;
    Bs[0][lk+2][lrow] = b4.z; Bs[0][lk+3][lrow] = b4.w;
    __syncthreads();

    for (int kt = 0; kt < KT; kt++) {
        int cur = kt & 1;
        if (kt + 1 < KT) {
            int k0 = (kt + 1) * 8;
            a4 = *(const float4*)&Az[(size_t)(bm + lrow) * K + k0 + lk];
            b4 = *(const float4*)&Bw[(size_t)(bn + lrow) * K + k0 + lk];
        }
#pragma unroll
        for (int k = 0; k < 8; k++) {
            ulonglong2 a01 = *(const ulonglong2*)&As[cur][k][tm];
            ulonglong2 a23 = *(const ulonglong2*)&As[cur][k][tm+4];
            float4 bv0 = *(const float4*)&Bs[cur][k][tn];
            float4 bv1 = *(const float4*)&Bs[cur][k][tn+4];
            u64 ap[4] = { a01.x, a01.y, a23.x, a23.y };
            u64 bs[8] = { splat2(bv0.x), splat2(bv0.y), splat2(bv0.z), splat2(bv0.w),
                          splat2(bv1.x), splat2(bv1.y), splat2(bv1.z), splat2(bv1.w) };
#pragma unroll
            for (int p = 0; p < 4; p++)
#pragma unroll
                for (int n = 0; n < 8; n++)
                    fma2(acc[p][n], ap[p], bs[n]);
        }
        if (kt + 1 < KT) {
            int nxt = cur ^ 1;
            As[nxt][lk+0][lrow] = a4.x; As[nxt][lk+1][lrow] = a4.y;
            As[nxt][lk+2][lrow] = a4.z; As[nxt][lk+3][lrow] = a4.w;
            Bs[nxt][lk+0][lrow] = b4.x; Bs[nxt][lk+1][lrow] = b4.y;
            Bs[nxt][lk+2][lrow] = b4.z; Bs[nxt][lk+3][lrow] = b4.w;
        }
        __syncthreads();
    }

    // epilogue: unpack pairs, add bias, store
    float bv[8];
#pragma unroll
    for (int n = 0; n < 8; n++) bv[n] = bias[bn + tn + n];
#pragma unroll
    for (int p = 0; p < 4; p++) {
        float r0[8], r1[8];
#pragma unroll
        for (int n = 0; n < 8; n++) {
            float lo, hi;
            asm("mov.b64 {%0, %1}, %2;" : "=f"(lo), "=f"(hi) : "l"(acc[p][n]));
            r0[n] = lo + bv[n]; r1[n] = hi + bv[n];
        }
        size_t row0 = (size_t)(bm + tm + 2*p) * N + bn + tn;
        size_t row1 = row0 + N;
        *(float4*)&Cz[row0]     = make_float4(r0[0], r0[1], r0[2], r0[3]);
        *(float4*)&Cz[row0 + 4] = make_float4(r0[4], r0[5], r0[6], r0[7]);
        *(float4*)&Cz[row1]     = make_float4(r1[0], r1[1], r1[2], r1[3]);
        *(float4*)&Cz[row1 + 4] = make_float4(r1[4], r1[5], r1[6], r1[7]);
    }
}

// ---------------- q = out@aw[:H], e = out@aw[H:] (warp per (b,l)) ----------
__global__ void k_qe(const float* __restrict__ attn_w)
{
    int r    = blockIdx.y;
    int w    = blockIdx.x * 8 + (threadIdx.x >> 5);  // 0..51199
    int lane = threadIdx.x & 31;
    const float* o = g_out + ((size_t)r * BL + w) * HDIM;
    float q = 0.f, e = 0.f;
#pragma unroll
    for (int h = lane * 8; h < lane * 8 + 8; h += 4) {
        float4 ov = *(const float4*)&o[h];
        float4 a1 = *(const float4*)&attn_w[h];
        float4 a2 = *(const float4*)&attn_w[HDIM + h];
        q += ov.x*a1.x + ov.y*a1.y + ov.z*a1.z + ov.w*a1.w;
        e += ov.x*a2.x + ov.y*a2.y + ov.z*a2.z + ov.w*a2.w;
    }
#pragma unroll
    for (int off = 16; off; off >>= 1) {
        q += __shfl_down_sync(0xffffffffu, q, off);
        e += __shfl_down_sync(0xffffffffu, e, off);
    }
    if (lane == 0) { g_q[r * BL + w] = q; g_e[r * BL + w] = e; }
}

// ---------------- windowed attention + concat for FC ----------------------
__global__ void k_attn()
{
    int r    = blockIdx.y;
    int bl95 = blockIdx.x;                 // 0..48639
    int b    = bl95 / MSEQ, l = bl95 % MSEQ;
    int h    = threadIdx.x;

    const float* qrow = g_q + r * BL + b * LSEQ;
    const float* erow = g_e + r * BL + b * LSEQ;
    float qv = qrow[l + WINW];
    float s[WINW];
    float mx = -1e30f;
#pragma unroll
    for (int k = 0; k < WINW; k++) { s[k] = qv + erow[l + k]; mx = fmaxf(mx, s[k]); }
    float sum = 0.f;
#pragma unroll
    for (int k = 0; k < WINW; k++) { s[k] = __expf(s[k] - mx); sum += s[k]; }
    float inv = 1.f / sum;

    const float* o = g_out + ((size_t)r * BL + b * LSEQ + l) * HDIM;
    float c = 0.f;
#pragma unroll
    for (int k = 0; k < WINW; k++) c += s[k] * inv * o[k * HDIM + h];

    size_t m = (size_t)r * BM95 + bl95;
    g_cat[m * (2*HDIM) + h]        = c;
    g_cat[m * (2*HDIM) + HDIM + h] = o[WINW * HDIM + h];
}

// ---------------- final head: concat(rnn1[b,l], rnn2[b,min(l+D,99)]) ------
__global__ void k_final(const float* __restrict__ outW, const float* __restrict__ outb,
                        float* __restrict__ out)
{
    int w    = blockIdx.x * 8 + (threadIdx.x >> 5);  // 0..51199
    int lane = threadIdx.x & 31;
    int b = w / LSEQ, l = w % LSEQ;

    const float* A1 = (l < WINW)
        ? (g_out   + ((size_t)(b * LSEQ + l)) * HDIM)
        : (g_fused + ((size_t)(b * MSEQ + l - WINW)) * HDIM);
    int lidx = min(l + DSH, LSEQ - 1);
    const float* A2 = (lidx < WINW)
        ? (g_out   + ((size_t)BL + b * LSEQ + lidx) * HDIM)
        : (g_fused + ((size_t)BM95 + b * MSEQ + lidx - WINW) * HDIM);

    float acc = 0.f;
#pragma unroll
    for (int h = lane * 8; h < lane * 8 + 8; h += 4) {
        float4 a  = *(const float4*)&A1[h];
        float4 w1 = *(const float4*)&outW[h];
        acc += a.x*w1.x + a.y*w1.y + a.z*w1.z + a.w*w1.w;
        float4 a2 = *(const float4*)&A2[h];
        float4 w2 = *(const float4*)&outW[HDIM + h];
        acc += a2.x*w2.x + a2.y*w2.y + a2.z*w2.z + a2.w*w2.w;
    }
#pragma unroll
    for (int off = 16; off; off >>= 1)
        acc += __shfl_down_sync(0xffffffffu, acc, off);
    if (lane == 0) out[w] = 1.f / (1.f + __expf(-(acc + outb[0])));
}

// ---------------------------------------------------------------------------
extern "C" void kernel_launch(void* const* d_in, const int* in_sizes, int n_in,
                              void* d_out, int out_size)
{
    const float* received = (const float*)d_in[0];
    const float* r1_Wih0  = (const float*)d_in[1];
    const float* r1_Whh0  = (const float*)d_in[2];
    const float* r1_bih0  = (const float*)d_in[3];
    const float* r1_bhh0  = (const float*)d_in[4];
    const float* r1_Wih1  = (const float*)d_in[5];
    const float* r1_Whh1  = (const float*)d_in[6];
    const float* r1_bih1  = (const float*)d_in[7];
    const float* r1_bhh1  = (const float*)d_in[8];
    const float* r2_Wih0  = (const float*)d_in[9];
    const float* r2_Whh0  = (const float*)d_in[10];
    const float* r2_bih0  = (const float*)d_in[11];
    const float* r2_bhh0  = (const float*)d_in[12];
    const float* r2_Wih1  = (const float*)d_in[13];
    const float* r2_Whh1  = (const float*)d_in[14];
    const float* r2_bih1  = (const float*)d_in[15];
    const float* r2_bhh1  = (const float*)d_in[16];
    const float* attn_w   = (const float*)d_in[17];
    const float* fc_W     = (const float*)d_in[18];
    const float* fc_b     = (const float*)d_in[19];
    const float* out_W    = (const float*)d_in[20];
    const float* out_b    = (const float*)d_in[21];
    float* out = (float*)d_out;

    float* d_xw1;   cudaGetSymbolAddress((void**)&d_xw1,   g_xw1);
    float* d_h1;    cudaGetSymbolAddress((void**)&d_h1,    g_h1);
    float* d_gout;  cudaGetSymbolAddress((void**)&d_gout,  g_out);
    float* d_cat;   cudaGetSymbolAddress((void**)&d_cat,   g_cat);
    float* d_fused; cudaGetSymbolAddress((void**)&d_fused, g_fused);

    // 1. transpose the four 768x256 recurrent matrices into float4-over-k layout
    k_prep<<<(4*64*G3 + 255)/256, 256>>>(r1_Whh0, r2_Whh0, r1_Whh1, r2_Whh1);
    // 2. layer-0 recurrence with fused input projection (both GRUs via grid.y)
    k_rec<1><<<dim3(BATCH/TB, 2), 256>>>((const float*)0, received,
                                         r1_Wih0, r2_Wih0, r1_bih0, r2_bih0,
                                         0, r1_bhh0, r2_bhh0, d_h1);
    // 3. layer-1 gate inputs: xw1 = h1 @ Wih1.T + bih1 (both GRUs via grid.z)
    k_gemm<<<dim3(G3/128, BL/128, 2), 256>>>(d_h1, (size_t)BL*HDIM,
                                             r1_Wih1, r2_Wih1, r1_bih1, r2_bih1,
                                             d_xw1, (size_t)BL*G3, G3, HDIM);
    // 4. layer-1 recurrence
    k_rec<0><<<dim3(BATCH/TB, 2), 256>>>(d_xw1, (const float*)0,
                                         (const float*)0, (const float*)0,
                                         (const float*)0, (const float*)0,
                                         2, r1_bhh1, r2_bhh1, d_gout);
    // 5. attention scalars q,e
    k_qe<<<dim3(BL/8, 2), 256>>>(attn_w);
    // 6. windowed softmax attention + concat
    k_attn<<<dim3(BM95, 2), 256>>>();
    // 7. FC over both branches stacked
    k_gemm<<<dim3(HDIM/128, (2*BM95)/128, 1), 256>>>(d_cat, 0,
                                                     fc_W, fc_W, fc_b, fc_b,
                                                     d_fused, 0, HDIM, 2*HDIM);
    // 8. final projection + sigmoid
    k_final<<<BL/8, 256>>>(out_W, out_b, out);
}

// round 4
// speedup vs baseline: 1.4888x; 1.0504x over previous
#include <cuda_runtime.h>
#include <math.h>

#define BATCH 512
#define LSEQ  100
#define NINPUT 3
#define HDIM  256
#define G3    768
#define DSH   10
#define WINW  5
#define MSEQ  95          // LSEQ - WINW
#define TB    8           // batch samples per recurrent block

#define BL    (BATCH*LSEQ)      // 51200
#define BM95  (BATCH*MSEQ)      // 48640

typedef unsigned long long u64;

// ---------------- scratch (static device memory; no allocations) ----------
__device__ float  g_xw1 [2*BL*G3];          // layer-1 gate inputs, per GRU
__device__ float  g_h1  [2*BL*HDIM];        // layer-0 outputs
__device__ float  g_out [2*BL*HDIM];        // layer-1 outputs (out1/out2)
__device__ float  g_q   [2*BL];
__device__ float  g_e   [2*BL];
__device__ float  g_cat [2*BM95*2*HDIM];    // [c, out_shift] concat for FC
__device__ float  g_fused[2*BM95*HDIM];     // FC output
__device__ float4 g_wT4 [4*64*G3];          // transposed Whh, float4 over k
// wT4 slots: 0=r1_Whh0 1=r2_Whh0 2=r1_Whh1 3=r2_Whh1

__device__ __forceinline__ float sigf(float x) { return 1.f / (1.f + __expf(-x)); }

// packed dual-fp32 FMA: acc.{lo,hi} += a.{lo,hi} * b.{lo,hi}
__device__ __forceinline__ void fma2(u64& acc, u64 a, u64 b) {
    asm("fma.rn.f32x2 %0, %1, %2, %0;" : "+l"(acc) : "l"(a), "l"(b));
}
__device__ __forceinline__ u64 splat2(float x) {
    u64 r; asm("mov.b64 %0, {%1, %1};" : "=l"(r) : "f"(x)); return r;
}
__device__ __forceinline__ float sum2(u64 v) {
    float lo, hi; asm("mov.b64 {%0, %1}, %2;" : "=f"(lo), "=f"(hi) : "l"(v));
    return lo + hi;
}

// ---------------- weight transpose: W[g][k] -> wT4[k/4][g] ----------------
__global__ void k_prep(const float* __restrict__ w0, const float* __restrict__ w1,
                       const float* __restrict__ w2, const float* __restrict__ w3)
{
    int idx = blockIdx.x * blockDim.x + threadIdx.x;
    if (idx >= 4 * 64 * G3) return;
    int g  = idx % G3;
    int k4 = (idx / G3) % 64;
    int m  = idx / (G3 * 64);
    const float* W = (m == 0) ? w0 : (m == 1) ? w1 : (m == 2) ? w2 : w3;
    const float* p = W + g * HDIM + 4 * k4;
    g_wT4[idx] = make_float4(p[0], p[1], p[2], p[3]);
}

// ---------------- GRU recurrence (512 threads, k-split halves) -------------
// FUSE=1: layer 0 — input projection (NINPUT=3) fused, weights in registers.
// FUSE=0: layer 1 — reads precomputed gate inputs xw_base (bias folded).
// Threads (kh, j): kh = tid>>8 selects k-half, j = tid&255 the gate column.
template<int FUSE>
__global__ void __launch_bounds__(512, 1)
k_rec(const float* __restrict__ xw_base, const float* __restrict__ xin,
      const float* __restrict__ Wih_0, const float* __restrict__ Wih_1,
      const float* __restrict__ bih_0, const float* __restrict__ bih_1,
      int wslot,
      const float* __restrict__ bhh_0, const float* __restrict__ bhh_1,
      float* __restrict__ hout_base)
{
    int r  = blockIdx.y;
    int tid = threadIdx.x;
    int j  = tid & 255;                   // gate/hidden index 0..255
    int kh = tid >> 8;                    // k half: 0 or 1
    int b0 = blockIdx.x * TB;
    const float*  bhh  = r ? bhh_1 : bhh_0;
    const float4* W    = g_wT4 + (size_t)(wslot + r) * (64 * G3) + kh * 32 * G3;
    const float*  xw   = xw_base ? (xw_base + (size_t)r * BL * G3) : (const float*)0;
    float*        hout = hout_base + (size_t)r * BL * HDIM;

    // fused input-projection weights (layer 0, kh==0 threads only)
    float wx[9], bx[3];
    if (FUSE && kh == 0) {
        const float* Wih = r ? Wih_1 : Wih_0;
        const float* bih = r ? bih_1 : bih_0;
#pragma unroll
        for (int g = 0; g < 3; g++) {
            wx[g*3+0] = Wih[(j + g*HDIM)*3 + 0];
            wx[g*3+1] = Wih[(j + g*HDIM)*3 + 1];
            wx[g*3+2] = Wih[(j + g*HDIM)*3 + 2];
            bx[g]     = bih[j + g*HDIM];
        }
    }

    __shared__ __align__(16) float hs[TB][HDIM];
    __shared__ float ps[3][TB][HDIM];     // kh=1 partial sums
    __shared__ float xs2[TB][4];
    if (kh == 0) {
#pragma unroll
        for (int b = 0; b < TB; b++) hs[b][j] = 0.f;
    }
    float bhr = bhh[j], bhz = bhh[j + HDIM], bhn = bhh[j + 2*HDIM];
    __syncthreads();

    for (int t = 0; t < LSEQ; t++) {
        if (FUSE && kh == 0 && j < TB * 3) {
            int b = j / 3, c = j % 3;
            xs2[b][c] = xin[((size_t)(b0 + b) * LSEQ + t) * NINPUT + c];
        }
        u64 ar[TB], az[TB], an[TB];
#pragma unroll
        for (int b = 0; b < TB; b++) { ar[b] = 0ull; az[b] = 0ull; an[b] = 0ull; }

        const float* hbase = &hs[0][0] + kh * 128;   // k offset: kh*32 k4 = 128 floats
#pragma unroll 4
        for (int kk = 0; kk < 32; kk++) {
            ulonglong2 w0 = *(const ulonglong2*)&W[kk*G3 + j];
            ulonglong2 w1 = *(const ulonglong2*)&W[kk*G3 + HDIM + j];
            ulonglong2 w2 = *(const ulonglong2*)&W[kk*G3 + 2*HDIM + j];
#pragma unroll
            for (int b = 0; b < TB; b++) {
                ulonglong2 h2 = *(const ulonglong2*)&hbase[b*HDIM + kk*4];
                fma2(ar[b], w0.x, h2.x); fma2(ar[b], w0.y, h2.y);
                fma2(az[b], w1.x, h2.x); fma2(az[b], w1.y, h2.y);
                fma2(an[b], w2.x, h2.x); fma2(an[b], w2.y, h2.y);
            }
        }
        if (kh == 1) {
#pragma unroll
            for (int b = 0; b < TB; b++) {
                ps[0][b][j] = sum2(ar[b]);
                ps[1][b][j] = sum2(az[b]);
                ps[2][b][j] = sum2(an[b]);
            }
        }
        __syncthreads();
        if (kh == 0) {
#pragma unroll
            for (int b = 0; b < TB; b++) {
                float gr, gz, gn;
                if (FUSE) {
                    float x0 = xs2[b][0], x1 = xs2[b][1], x2 = xs2[b][2];
                    gr = bx[0] + x0*wx[0] + x1*wx[1] + x2*wx[2];
                    gz = bx[1] + x0*wx[3] + x1*wx[4] + x2*wx[5];
                    gn = bx[2] + x0*wx[6] + x1*wx[7] + x2*wx[8];
                } else {
                    size_t base = ((size_t)(b0 + b) * LSEQ + t) * G3;
                    gr = xw[base + j];
                    gz = xw[base + HDIM + j];
                    gn = xw[base + 2*HDIM + j];
                }
                float rg = sigf(gr + sum2(ar[b]) + ps[0][b][j] + bhr);
                float zg = sigf(gz + sum2(az[b]) + ps[1][b][j] + bhz);
                float ng = tanhf(gn + rg * (sum2(an[b]) + ps[2][b][j] + bhn));
                float hn = (1.f - zg) * ng + zg * hs[b][j];
                hs[b][j] = hn;
                hout[((size_t)(b0 + b) * LSEQ + t) * HDIM + j] = hn;
            }
        }
        __syncthreads();
    }
}

// ---------------- SGEMM: C[M,N] = A[M,K] @ B[N,K].T + bias ----------------
// 128x128 block tile, 256 threads, 8x8 per thread (f32x2), double-buffered.
// M % 128 == 0, N % 128 == 0, K % 8 == 0. z selects (A,B,bias,C) set.
__global__ void __launch_bounds__(256, 2)
k_gemm(const float* __restrict__ A, size_t strideAz,
       const float* __restrict__ B0, const float* __restrict__ B1,
       const float* __restrict__ bias0, const float* __restrict__ bias1,
       float* __restrict__ C, size_t strideCz,
       int N, int K)
{
    int z = blockIdx.z;
    const float* Az   = A + (size_t)z * strideAz;
    const float* Bw   = z ? B1 : B0;
    const float* bias = z ? bias1 : bias0;
    float*       Cz   = C + (size_t)z * strideCz;

    __shared__ __align__(16) float As[2][8][128];
    __shared__ __align__(16) float Bs[2][8][128];

    int bm = blockIdx.y * 128;
    int bn = blockIdx.x * 128;
    int tid = threadIdx.x;

    int lrow = tid >> 1;
    int lk   = (tid & 1) * 4;
    int tm = (tid >> 4) * 8;
    int tn = (tid & 15) * 8;

    u64 acc[4][8];   // 4 M-pairs x 8 N
#pragma unroll
    for (int p = 0; p < 4; p++)
#pragma unroll
        for (int n = 0; n < 8; n++) acc[p][n] = 0ull;

    const int KT = K >> 3;

    float4 a4 = *(const float4*)&Az[(size_t)(bm + lrow) * K + lk];
    float4 b4 = *(const float4*)&Bw[(size_t)(bn + lrow) * K + lk];
    As[0][lk+0][lrow] = a4.x; As[0][lk+1][lrow] = a4.y;
    As[0][lk+2][lrow] = a4.z; As[0][lk+3][lrow] = a4.w;
    Bs[0][lk+0][lrow] = b4.x; Bs[0][lk+1][lrow] = b4.y;
    Bs[0][lk+2][lrow] = b4.z; Bs[0][lk+3][lrow] = b4.w;
    __syncthreads();

    for (int kt = 0; kt < KT; kt++) {
        int cur = kt & 1;
        if (kt + 1 < KT) {
            int k0 = (kt + 1) * 8;
            a4 = *(const float4*)&Az[(size_t)(bm + lrow) * K + k0 + lk];
            b4 = *(const float4*)&Bw[(size_t)(bn + lrow) * K + k0 + lk];
        }
#pragma unroll
        for (int k = 0; k < 8; k++) {
            ulonglong2 a01 = *(const ulonglong2*)&As[cur][k][tm];
            ulonglong2 a23 = *(const ulonglong2*)&As[cur][k][tm+4];
            float4 bv0 = *(const float4*)&Bs[cur][k][tn];
            float4 bv1 = *(const float4*)&Bs[cur][k][tn+4];
            u64 ap[4] = { a01.x, a01.y, a23.x, a23.y };
            u64 bs[8] = { splat2(bv0.x), splat2(bv0.y), splat2(bv0.z), splat2(bv0.w),
                          splat2(bv1.x), splat2(bv1.y), splat2(bv1.z), splat2(bv1.w) };
#pragma unroll
            for (int p = 0; p < 4; p++)
#pragma unroll
                for (int n = 0; n < 8; n++)
                    fma2(acc[p][n], ap[p], bs[n]);
        }
        if (kt + 1 < KT) {
            int nxt = cur ^ 1;
            As[nxt][lk+0][lrow] = a4.x; As[nxt][lk+1][lrow] = a4.y;
            As[nxt][lk+2][lrow] = a4.z; As[nxt][lk+3][lrow] = a4.w;
            Bs[nxt][lk+0][lrow] = b4.x; Bs[nxt][lk+1][lrow] = b4.y;
            Bs[nxt][lk+2][lrow] = b4.z; Bs[nxt][lk+3][lrow] = b4.w;
        }
        __syncthreads();
    }

    float bv[8];
#pragma unroll
    for (int n = 0; n < 8; n++) bv[n] = bias[bn + tn + n];
#pragma unroll
    for (int p = 0; p < 4; p++) {
        float r0[8], r1[8];
#pragma unroll
        for (int n = 0; n < 8; n++) {
            float lo, hi;
            asm("mov.b64 {%0, %1}, %2;" : "=f"(lo), "=f"(hi) : "l"(acc[p][n]));
            r0[n] = lo + bv[n]; r1[n] = hi + bv[n];
        }
        size_t row0 = (size_t)(bm + tm + 2*p) * N + bn + tn;
        size_t row1 = row0 + N;
        *(float4*)&Cz[row0]     = make_float4(r0[0], r0[1], r0[2], r0[3]);
        *(float4*)&Cz[row0 + 4] = make_float4(r0[4], r0[5], r0[6], r0[7]);
        *(float4*)&Cz[row1]     = make_float4(r1[0], r1[1], r1[2], r1[3]);
        *(float4*)&Cz[row1 + 4] = make_float4(r1[4], r1[5], r1[6], r1[7]);
    }
}

// ---------------- q = out@aw[:H], e = out@aw[H:] (warp per (b,l)) ----------
__global__ void k_qe(const float* __restrict__ attn_w)
{
    int r    = blockIdx.y;
    int w    = blockIdx.x * 8 + (threadIdx.x >> 5);  // 0..51199
    int lane = threadIdx.x & 31;
    const float* o = g_out + ((size_t)r * BL + w) * HDIM;
    float q = 0.f, e = 0.f;
#pragma unroll
    for (int h = lane * 8; h < lane * 8 + 8; h += 4) {
        float4 ov = *(const float4*)&o[h];
        float4 a1 = *(const float4*)&attn_w[h];
        float4 a2 = *(const float4*)&attn_w[HDIM + h];
        q += ov.x*a1.x + ov.y*a1.y + ov.z*a1.z + ov.w*a1.w;
        e += ov.x*a2.x + ov.y*a2.y + ov.z*a2.z + ov.w*a2.w;
    }
#pragma unroll
    for (int off = 16; off; off >>= 1) {
        q += __shfl_down_sync(0xffffffffu, q, off);
        e += __shfl_down_sync(0xffffffffu, e, off);
    }
    if (lane == 0) { g_q[r * BL + w] = q; g_e[r * BL + w] = e; }
}

// ---------------- windowed attention + concat for FC ----------------------
__global__ void k_attn()
{
    int r    = blockIdx.y;
    int bl95 = blockIdx.x;                 // 0..48639
    int b    = bl95 / MSEQ, l = bl95 % MSEQ;
    int h    = threadIdx.x;

    const float* qrow = g_q + r * BL + b * LSEQ;
    const float* erow = g_e + r * BL + b * LSEQ;
    float qv = qrow[l + WINW];
    float s[WINW];
    float mx = -1e30f;
#pragma unroll
    for (int k = 0; k < WINW; k++) { s[k] = qv + erow[l + k]; mx = fmaxf(mx, s[k]); }
    float sum = 0.f;
#pragma unroll
    for (int k = 0; k < WINW; k++) { s[k] = __expf(s[k] - mx); sum += s[k]; }
    float inv = 1.f / sum;

    const float* o = g_out + ((size_t)r * BL + b * LSEQ + l) * HDIM;
    float c = 0.f;
#pragma unroll
    for (int k = 0; k < WINW; k++) c += s[k] * inv * o[k * HDIM + h];

    size_t m = (size_t)r * BM95 + bl95;
    g_cat[m * (2*HDIM) + h]        = c;
    g_cat[m * (2*HDIM) + HDIM + h] = o[WINW * HDIM + h];
}

// ---------------- final head: concat(rnn1[b,l], rnn2[b,min(l+D,99)]) ------
__global__ void k_final(const float* __restrict__ outW, const float* __restrict__ outb,
                        float* __restrict__ out)
{
    int w    = blockIdx.x * 8 + (threadIdx.x >> 5);  // 0..51199
    int lane = threadIdx.x & 31;
    int b = w / LSEQ, l = w % LSEQ;

    const float* A1 = (l < WINW)
        ? (g_out   + ((size_t)(b * LSEQ + l)) * HDIM)
        : (g_fused + ((size_t)(b * MSEQ + l - WINW)) * HDIM);
    int lidx = min(l + DSH, LSEQ - 1);
    const float* A2 = (lidx < WINW)
        ? (g_out   + ((size_t)BL + b * LSEQ + lidx) * HDIM)
        : (g_fused + ((size_t)BM95 + b * MSEQ + lidx - WINW) * HDIM);

    float acc = 0.f;
#pragma unroll
    for (int h = lane * 8; h < lane * 8 + 8; h += 4) {
        float4 a  = *(const float4*)&A1[h];
        float4 w1 = *(const float4*)&outW[h];
        acc += a.x*w1.x + a.y*w1.y + a.z*w1.z + a.w*w1.w;
        float4 a2 = *(const float4*)&A2[h];
        float4 w2 = *(const float4*)&outW[HDIM + h];
        acc += a2.x*w2.x + a2.y*w2.y + a2.z*w2.z + a2.w*w2.w;
    }
#pragma unroll
    for (int off = 16; off; off >>= 1)
        acc += __shfl_down_sync(0xffffffffu, acc, off);
    if (lane == 0) out[w] = 1.f / (1.f + __expf(-(acc + outb[0])));
}

// ---------------------------------------------------------------------------
extern "C" void kernel_launch(void* const* d_in, const int* in_sizes, int n_in,
                              void* d_out, int out_size)
{
    const float* received = (const float*)d_in[0];
    const float* r1_Wih0  = (const float*)d_in[1];
    const float* r1_Whh0  = (const float*)d_in[2];
    const float* r1_bih0  = (const float*)d_in[3];
    const float* r1_bhh0  = (const float*)d_in[4];
    const float* r1_Wih1  = (const float*)d_in[5];
    const float* r1_Whh1  = (const float*)d_in[6];
    const float* r1_bih1  = (const float*)d_in[7];
    const float* r1_bhh1  = (const float*)d_in[8];
    const float* r2_Wih0  = (const float*)d_in[9];
    const float* r2_Whh0  = (const float*)d_in[10];
    const float* r2_bih0  = (const float*)d_in[11];
    const float* r2_bhh0  = (const float*)d_in[12];
    const float* r2_Wih1  = (const float*)d_in[13];
    const float* r2_Whh1  = (const float*)d_in[14];
    const float* r2_bih1  = (const float*)d_in[15];
    const float* r2_bhh1  = (const float*)d_in[16];
    const float* attn_w   = (const float*)d_in[17];
    const float* fc_W     = (const float*)d_in[18];
    const float* fc_b     = (const float*)d_in[19];
    const float* out_W    = (const float*)d_in[20];
    const float* out_b    = (const float*)d_in[21];
    float* out = (float*)d_out;

    float* d_xw1;   cudaGetSymbolAddress((void**)&d_xw1,   g_xw1);
    float* d_h1;    cudaGetSymbolAddress((void**)&d_h1,    g_h1);
    float* d_gout;  cudaGetSymbolAddress((void**)&d_gout,  g_out);
    float* d_cat;   cudaGetSymbolAddress((void**)&d_cat,   g_cat);
    float* d_fused; cudaGetSymbolAddress((void**)&d_fused, g_fused);

    // 1. transpose the four 768x256 recurrent matrices into float4-over-k layout
    k_prep<<<(4*64*G3 + 255)/256, 256>>>(r1_Whh0, r2_Whh0, r1_Whh1, r2_Whh1);
    // 2. layer-0 recurrence with fused input projection (both GRUs via grid.y)
    k_rec<1><<<dim3(BATCH/TB, 2), 512>>>((const float*)0, received,
                                         r1_Wih0, r2_Wih0, r1_bih0, r2_bih0,
                                         0, r1_bhh0, r2_bhh0, d_h1);
    // 3. layer-1 gate inputs: xw1 = h1 @ Wih1.T + bih1 (both GRUs via grid.z)
    k_gemm<<<dim3(G3/128, BL/128, 2), 256>>>(d_h1, (size_t)BL*HDIM,
                                             r1_Wih1, r2_Wih1, r1_bih1, r2_bih1,
                                             d_xw1, (size_t)BL*G3, G3, HDIM);
    // 4. layer-1 recurrence
    k_rec<0><<<dim3(BATCH/TB, 2), 512>>>(d_xw1, (const float*)0,
                                         (const float*)0, (const float*)0,
                                         (const float*)0, (const float*)0,
                                         2, r1_bhh1, r2_bhh1, d_gout);
    // 5. attention scalars q,e
    k_qe<<<dim3(BL/8, 2), 256>>>(attn_w);
    // 6. windowed softmax attention + concat
    k_attn<<<dim3(BM95, 2), 256>>>();
    // 7. FC over both branches stacked
    k_gemm<<<dim3(HDIM/128, (2*BM95)/128, 1), 256>>>(d_cat, 0,
                                                     fc_W, fc_W, fc_b, fc_b,
                                                     d_fused, 0, HDIM, 2*HDIM);
    // 8. final projection + sigmoid
    k_final<<<BL/8, 256>>>(out_W, out_b, out);
}

// round 5
// speedup vs baseline: 1.6561x; 1.1124x over previous
#include <cuda_runtime.h>
#include <math.h>

#define BATCH 512
#define LSEQ  100
#define NINPUT 3
#define HDIM  256
#define G3    768
#define DSH   10
#define WINW  5
#define MSEQ  95          // LSEQ - WINW
#define TB    8           // batch samples per recurrent block

#define BL    (BATCH*LSEQ)      // 51200
#define BM95  (BATCH*MSEQ)      // 48640

typedef unsigned long long u64;

// ---------------- scratch (static device memory; no allocations) ----------
__device__ float  g_xw1 [2*BL*G3];          // layer-1 gate inputs, per GRU
__device__ float  g_h1  [2*BL*HDIM];        // layer-0 outputs
__device__ float  g_out [2*BL*HDIM];        // layer-1 outputs (out1/out2)
__device__ float  g_q   [2*BL];
__device__ float  g_e   [2*BL];
__device__ float  g_cat [2*BM95*2*HDIM];    // [c, out_shift] concat for FC
__device__ float  g_fused[2*BM95*HDIM];     // FC output
__device__ float4 g_wT4 [4*64*G3];          // transposed Whh, float4 over k
// wT4 slots: 0=r1_Whh0 1=r2_Whh0 2=r1_Whh1 3=r2_Whh1

__device__ __forceinline__ float sigf(float x) { return 1.f / (1.f + __expf(-x)); }

// packed dual-fp32 FMA: acc.{lo,hi} += a.{lo,hi} * b.{lo,hi}
__device__ __forceinline__ void fma2(u64& acc, u64 a, u64 b) {
    asm("fma.rn.f32x2 %0, %1, %2, %0;" : "+l"(acc) : "l"(a), "l"(b));
}
__device__ __forceinline__ u64 splat2(float x) {
    u64 r; asm("mov.b64 %0, {%1, %1};" : "=l"(r) : "f"(x)); return r;
}
__device__ __forceinline__ float sum2(u64 v) {
    float lo, hi; asm("mov.b64 {%0, %1}, %2;" : "=f"(lo), "=f"(hi) : "l"(v));
    return lo + hi;
}

// ---------------- weight transpose: W[g][k] -> wT4[k/4][g] ----------------
__global__ void k_prep(const float* __restrict__ w0, const float* __restrict__ w1,
                       const float* __restrict__ w2, const float* __restrict__ w3)
{
    int idx = blockIdx.x * blockDim.x + threadIdx.x;
    if (idx >= 4 * 64 * G3) return;
    int g  = idx % G3;
    int k4 = (idx / G3) % 64;
    int m  = idx / (G3 * 64);
    const float* W = (m == 0) ? w0 : (m == 1) ? w1 : (m == 2) ? w2 : w3;
    const float* p = W + g * HDIM + 4 * k4;
    g_wT4[idx] = make_float4(p[0], p[1], p[2], p[3]);
}

// ---------------- GRU recurrence (512 threads, k-split, pipelined xw) ------
// FUSE=1: layer 0 — input projection (NINPUT=3) fused, weights in registers.
// FUSE=0: layer 1 — reads precomputed gate inputs xw_base (bias folded),
//         software-pipelined one step ahead in registers.
// Threads (kh, j): kh = tid>>8 selects k-half, j = tid&255 the gate column.
// Pointwise phase is split: half kh updates batch samples [4kh, 4kh+4).
template<int FUSE>
__global__ void __launch_bounds__(512, 1)
k_rec(const float* __restrict__ xw_base, const float* __restrict__ xin,
      const float* __restrict__ Wih_0, const float* __restrict__ Wih_1,
      const float* __restrict__ bih_0, const float* __restrict__ bih_1,
      int wslot,
      const float* __restrict__ bhh_0, const float* __restrict__ bhh_1,
      float* __restrict__ hout_base)
{
    int r  = blockIdx.y;
    int tid = threadIdx.x;
    int j  = tid & 255;                   // gate/hidden index 0..255
    int kh = tid >> 8;                    // k half: 0 or 1
    int b0 = blockIdx.x * TB;
    const float*  bhh  = r ? bhh_1 : bhh_0;
    const float4* W    = g_wT4 + (size_t)(wslot + r) * (64 * G3) + kh * 32 * G3;
    const float*  xw   = xw_base ? (xw_base + (size_t)r * BL * G3) : (const float*)0;
    float*        hout = hout_base + (size_t)r * BL * HDIM;

    int bown = kh * 4;                    // batch samples this half updates
    // fused input-projection weights (layer 0; all threads — both halves update)
    float wx[9], bx[3];
    if (FUSE) {
        const float* Wih = r ? Wih_1 : Wih_0;
        const float* bih = r ? bih_1 : bih_0;
#pragma unroll
        for (int g = 0; g < 3; g++) {
            wx[g*3+0] = Wih[(j + g*HDIM)*3 + 0];
            wx[g*3+1] = Wih[(j + g*HDIM)*3 + 1];
            wx[g*3+2] = Wih[(j + g*HDIM)*3 + 2];
            bx[g]     = bih[j + g*HDIM];
        }
    }

    __shared__ __align__(16) float hs[TB][HDIM];
    __shared__ float ps[2][3][4][HDIM];   // [writer-half][gate][i][j] partials
    float* ps_w       = &ps[kh][0][0][0];
    const float* ps_r = &ps[1 - kh][0][0][0];

#pragma unroll
    for (int i = 0; i < 4; i++) hs[bown + i][j] = 0.f;
    float bhr = bhh[j], bhz = bhh[j + HDIM], bhn = bhh[j + 2*HDIM];

    // prologue: pipeline registers hold this half's step-0 gate inputs
    float xg[12];
    if (FUSE) {
#pragma unroll
        for (int i = 0; i < 4; i++) {
            size_t base = ((size_t)(b0 + bown + i) * LSEQ + 0) * NINPUT;
            xg[i*3+0] = xin[base+0]; xg[i*3+1] = xin[base+1]; xg[i*3+2] = xin[base+2];
        }
    } else {
#pragma unroll
        for (int i = 0; i < 4; i++) {
            size_t base = ((size_t)(b0 + bown + i) * LSEQ + 0) * G3;
            xg[i*3+0] = xw[base + j];
            xg[i*3+1] = xw[base + HDIM + j];
            xg[i*3+2] = xw[base + 2*HDIM + j];
        }
    }
    __syncthreads();

    const float* hb_own = &hs[bown][0]     + kh * 128;
    const float* hb_oth = &hs[4 - bown][0] + kh * 128;

    for (int t = 0; t < LSEQ; t++) {
        u64 arO[4], azO[4], anO[4], arX[4], azX[4], anX[4];
#pragma unroll
        for (int i = 0; i < 4; i++) {
            arO[i]=0ull; azO[i]=0ull; anO[i]=0ull;
            arX[i]=0ull; azX[i]=0ull; anX[i]=0ull;
        }

#pragma unroll 4
        for (int kk = 0; kk < 32; kk++) {
            ulonglong2 w0 = *(const ulonglong2*)&W[kk*G3 + j];
            ulonglong2 w1 = *(const ulonglong2*)&W[kk*G3 + HDIM + j];
            ulonglong2 w2 = *(const ulonglong2*)&W[kk*G3 + 2*HDIM + j];
#pragma unroll
            for (int i = 0; i < 4; i++) {
                ulonglong2 h2 = *(const ulonglong2*)&hb_own[i*HDIM + kk*4];
                fma2(arO[i], w0.x, h2.x); fma2(arO[i], w0.y, h2.y);
                fma2(azO[i], w1.x, h2.x); fma2(azO[i], w1.y, h2.y);
                fma2(anO[i], w2.x, h2.x); fma2(anO[i], w2.y, h2.y);
            }
#pragma unroll
            for (int i = 0; i < 4; i++) {
                ulonglong2 h2 = *(const ulonglong2*)&hb_oth[i*HDIM + kk*4];
                fma2(arX[i], w0.x, h2.x); fma2(arX[i], w0.y, h2.y);
                fma2(azX[i], w1.x, h2.x); fma2(azX[i], w1.y, h2.y);
                fma2(anX[i], w2.x, h2.x); fma2(anX[i], w2.y, h2.y);
            }
        }
        // export partials for the OTHER half's samples
#pragma unroll
        for (int i = 0; i < 4; i++) {
            ps_w[0*4*HDIM + i*HDIM + j] = sum2(arX[i]);
            ps_w[1*4*HDIM + i*HDIM + j] = sum2(azX[i]);
            ps_w[2*4*HDIM + i*HDIM + j] = sum2(anX[i]);
        }
        __syncthreads();

        // pointwise update for this half's 4 samples
#pragma unroll
        for (int i = 0; i < 4; i++) {
            float gr, gz, gn;
            if (FUSE) {
                float x0 = xg[i*3+0], x1 = xg[i*3+1], x2 = xg[i*3+2];
                gr = bx[0] + x0*wx[0] + x1*wx[1] + x2*wx[2];
                gz = bx[1] + x0*wx[3] + x1*wx[4] + x2*wx[5];
                gn = bx[2] + x0*wx[6] + x1*wx[7] + x2*wx[8];
            } else {
                gr = xg[i*3+0]; gz = xg[i*3+1]; gn = xg[i*3+2];
            }
            float rg = sigf(gr + sum2(arO[i]) + ps_r[0*4*HDIM + i*HDIM + j] + bhr);
            float zg = sigf(gz + sum2(azO[i]) + ps_r[1*4*HDIM + i*HDIM + j] + bhz);
            float ng = tanhf(gn + rg * (sum2(anO[i]) + ps_r[2*4*HDIM + i*HDIM + j] + bhn));
            float hn = (1.f - zg) * ng + zg * hs[bown + i][j];
            hs[bown + i][j] = hn;
            hout[((size_t)(b0 + bown + i) * LSEQ + t) * HDIM + j] = hn;
        }
        // prefetch next step's gate inputs (consumed after next FMA phase)
        if (t + 1 < LSEQ) {
            if (FUSE) {
#pragma unroll
                for (int i = 0; i < 4; i++) {
                    size_t base = ((size_t)(b0 + bown + i) * LSEQ + (t+1)) * NINPUT;
                    xg[i*3+0] = xin[base+0]; xg[i*3+1] = xin[base+1]; xg[i*3+2] = xin[base+2];
                }
            } else {
#pragma unroll
                for (int i = 0; i < 4; i++) {
                    size_t base = ((size_t)(b0 + bown + i) * LSEQ + (t+1)) * G3;
                    xg[i*3+0] = xw[base + j];
                    xg[i*3+1] = xw[base + HDIM + j];
                    xg[i*3+2] = xw[base + 2*HDIM + j];
                }
            }
        }
        __syncthreads();
    }
}

// ---------------- SGEMM: C[M,N] = A[M,K] @ B[N,K].T + bias ----------------
// 128x128 block tile, 256 threads, 8x8 per thread (f32x2), double-buffered.
// M % 128 == 0, N % 128 == 0, K % 8 == 0. z selects (A,B,bias,C) set.
__global__ void __launch_bounds__(256, 2)
k_gemm(const float* __restrict__ A, size_t strideAz,
       const float* __restrict__ B0, const float* __restrict__ B1,
       const float* __restrict__ bias0, const float* __restrict__ bias1,
       float* __restrict__ C, size_t strideCz,
       int N, int K)
{
    int z = blockIdx.z;
    const float* Az   = A + (size_t)z * strideAz;
    const float* Bw   = z ? B1 : B0;
    const float* bias = z ? bias1 : bias0;
    float*       Cz   = C + (size_t)z * strideCz;

    __shared__ __align__(16) float As[2][8][128];
    __shared__ __align__(16) float Bs[2][8][128];

    int bm = blockIdx.y * 128;
    int bn = blockIdx.x * 128;
    int tid = threadIdx.x;

    int lrow = tid >> 1;
    int lk   = (tid & 1) * 4;
    int tm = (tid >> 4) * 8;
    int tn = (tid & 15) * 8;

    u64 acc[4][8];   // 4 M-pairs x 8 N
#pragma unroll
    for (int p = 0; p < 4; p++)
#pragma unroll
        for (int n = 0; n < 8; n++) acc[p][n] = 0ull;

    const int KT = K >> 3;

    float4 a4 = *(const float4*)&Az[(size_t)(bm + lrow) * K + lk];
    float4 b4 = *(const float4*)&Bw[(size_t)(bn + lrow) * K + lk];
    As[0][lk+0][lrow] = a4.x; As[0][lk+1][lrow] = a4.y;
    As[0][lk+2][lrow] = a4.z; As[0][lk+3][lrow] = a4.w;
    Bs[0][lk+0][lrow] = b4.x; Bs[0][lk+1][lrow] = b4.y;
    Bs[0][lk+2][lrow] = b4.z; Bs[0][lk+3][lrow] = b4.w;
    __syncthreads();

    for (int kt = 0; kt < KT; kt++) {
        int cur = kt & 1;
        if (kt + 1 < KT) {
            int k0 = (kt + 1) * 8;
            a4 = *(const float4*)&Az[(size_t)(bm + lrow) * K + k0 + lk];
            b4 = *(const float4*)&Bw[(size_t)(bn + lrow) * K + k0 + lk];
        }
#pragma unroll
        for (int k = 0; k < 8; k++) {
            ulonglong2 a01 = *(const ulonglong2*)&As[cur][k][tm];
            ulonglong2 a23 = *(const ulonglong2*)&As[cur][k][tm+4];
            float4 bv0 = *(const float4*)&Bs[cur][k][tn];
            float4 bv1 = *(const float4*)&Bs[cur][k][tn+4];
            u64 ap[4] = { a01.x, a01.y, a23.x, a23.y };
            u64 bs[8] = { splat2(bv0.x), splat2(bv0.y), splat2(bv0.z), splat2(bv0.w),
                          splat2(bv1.x), splat2(bv1.y), splat2(bv1.z), splat2(bv1.w) };
#pragma unroll
            for (int p = 0; p < 4; p++)
#pragma unroll
                for (int n = 0; n < 8; n++)
                    fma2(acc[p][n], ap[p], bs[n]);
        }
        if (kt + 1 < KT) {
            int nxt = cur ^ 1;
            As[nxt][lk+0][lrow] = a4.x; As[nxt][lk+1][lrow] = a4.y;
            As[nxt][lk+2][lrow] = a4.z; As[nxt][lk+3][lrow] = a4.w;
            Bs[nxt][lk+0][lrow] = b4.x; Bs[nxt][lk+1][lrow] = b4.y;
            Bs[nxt][lk+2][lrow] = b4.z; Bs[nxt][lk+3][lrow] = b4.w;
        }
        __syncthreads();
    }

    float bv[8];
#pragma unroll
    for (int n = 0; n < 8; n++) bv[n] = bias[bn + tn + n];
#pragma unroll
    for (int p = 0; p < 4; p++) {
        float r0[8], r1[8];
#pragma unroll
        for (int n = 0; n < 8; n++) {
            float lo, hi;
            asm("mov.b64 {%0, %1}, %2;" : "=f"(lo), "=f"(hi) : "l"(acc[p][n]));
            r0[n] = lo + bv[n]; r1[n] = hi + bv[n];
        }
        size_t row0 = (size_t)(bm + tm + 2*p) * N + bn + tn;
        size_t row1 = row0 + N;
        *(float4*)&Cz[row0]     = make_float4(r0[0], r0[1], r0[2], r0[3]);
        *(float4*)&Cz[row0 + 4] = make_float4(r0[4], r0[5], r0[6], r0[7]);
        *(float4*)&Cz[row1]     = make_float4(r1[0], r1[1], r1[2], r1[3]);
        *(float4*)&Cz[row1 + 4] = make_float4(r1[4], r1[5], r1[6], r1[7]);
    }
}

// ---------------- q = out@aw[:H], e = out@aw[H:] (warp per (b,l)) ----------
__global__ void k_qe(const float* __restrict__ attn_w)
{
    int r    = blockIdx.y;
    int w    = blockIdx.x * 8 + (threadIdx.x >> 5);  // 0..51199
    int lane = threadIdx.x & 31;
    const float* o = g_out + ((size_t)r * BL + w) * HDIM;
    float q = 0.f, e = 0.f;
#pragma unroll
    for (int h = lane * 8; h < lane * 8 + 8; h += 4) {
        float4 ov = *(const float4*)&o[h];
        float4 a1 = *(const float4*)&attn_w[h];
        float4 a2 = *(const float4*)&attn_w[HDIM + h];
        q += ov.x*a1.x + ov.y*a1.y + ov.z*a1.z + ov.w*a1.w;
        e += ov.x*a2.x + ov.y*a2.y + ov.z*a2.z + ov.w*a2.w;
    }
#pragma unroll
    for (int off = 16; off; off >>= 1) {
        q += __shfl_down_sync(0xffffffffu, q, off);
        e += __shfl_down_sync(0xffffffffu, e, off);
    }
    if (lane == 0) { g_q[r * BL + w] = q; g_e[r * BL + w] = e; }
}

// ---------------- windowed attention + concat for FC ----------------------
__global__ void k_attn()
{
    int r    = blockIdx.y;
    int bl95 = blockIdx.x;                 // 0..48639
    int b    = bl95 / MSEQ, l = bl95 % MSEQ;
    int h    = threadIdx.x;

    const float* qrow = g_q + r * BL + b * LSEQ;
    const float* erow = g_e + r * BL + b * LSEQ;
    float qv = qrow[l + WINW];
    float s[WINW];
    float mx = -1e30f;
#pragma unroll
    for (int k = 0; k < WINW; k++) { s[k] = qv + erow[l + k]; mx = fmaxf(mx, s[k]); }
    float sum = 0.f;
#pragma unroll
    for (int k = 0; k < WINW; k++) { s[k] = __expf(s[k] - mx); sum += s[k]; }
    float inv = 1.f / sum;

    const float* o = g_out + ((size_t)r * BL + b * LSEQ + l) * HDIM;
    float c = 0.f;
#pragma unroll
    for (int k = 0; k < WINW; k++) c += s[k] * inv * o[k * HDIM + h];

    size_t m = (size_t)r * BM95 + bl95;
    g_cat[m * (2*HDIM) + h]        = c;
    g_cat[m * (2*HDIM) + HDIM + h] = o[WINW * HDIM + h];
}

// ---------------- final head: concat(rnn1[b,l], rnn2[b,min(l+D,99)]) ------
__global__ void k_final(const float* __restrict__ outW, const float* __restrict__ outb,
                        float* __restrict__ out)
{
    int w    = blockIdx.x * 8 + (threadIdx.x >> 5);  // 0..51199
    int lane = threadIdx.x & 31;
    int b = w / LSEQ, l = w % LSEQ;

    const float* A1 = (l < WINW)
        ? (g_out   + ((size_t)(b * LSEQ + l)) * HDIM)
        : (g_fused + ((size_t)(b * MSEQ + l - WINW)) * HDIM);
    int lidx = min(l + DSH, LSEQ - 1);
    const float* A2 = (lidx < WINW)
        ? (g_out   + ((size_t)BL + b * LSEQ + lidx) * HDIM)
        : (g_fused + ((size_t)BM95 + b * MSEQ + lidx - WINW) * HDIM);

    float acc = 0.f;
#pragma unroll
    for (int h = lane * 8; h < lane * 8 + 8; h += 4) {
        float4 a  = *(const float4*)&A1[h];
        float4 w1 = *(const float4*)&outW[h];
        acc += a.x*w1.x + a.y*w1.y + a.z*w1.z + a.w*w1.w;
        float4 a2 = *(const float4*)&A2[h];
        float4 w2 = *(const float4*)&outW[HDIM + h];
        acc += a2.x*w2.x + a2.y*w2.y + a2.z*w2.z + a2.w*w2.w;
    }
#pragma unroll
    for (int off = 16; off; off >>= 1)
        acc += __shfl_down_sync(0xffffffffu, acc, off);
    if (lane == 0) out[w] = 1.f / (1.f + __expf(-(acc + outb[0])));
}

// ---------------------------------------------------------------------------
extern "C" void kernel_launch(void* const* d_in, const int* in_sizes, int n_in,
                              void* d_out, int out_size)
{
    const float* received = (const float*)d_in[0];
    const float* r1_Wih0  = (const float*)d_in[1];
    const float* r1_Whh0  = (const float*)d_in[2];
    const float* r1_bih0  = (const float*)d_in[3];
    const float* r1_bhh0  = (const float*)d_in[4];
    const float* r1_Wih1  = (const float*)d_in[5];
    const float* r1_Whh1  = (const float*)d_in[6];
    const float* r1_bih1  = (const float*)d_in[7];
    const float* r1_bhh1  = (const float*)d_in[8];
    const float* r2_Wih0  = (const float*)d_in[9];
    const float* r2_Whh0  = (const float*)d_in[10];
    const float* r2_bih0  = (const float*)d_in[11];
    const float* r2_bhh0  = (const float*)d_in[12];
    const float* r2_Wih1  = (const float*)d_in[13];
    const float* r2_Whh1  = (const float*)d_in[14];
    const float* r2_bih1  = (const float*)d_in[15];
    const float* r2_bhh1  = (const float*)d_in[16];
    const float* attn_w   = (const float*)d_in[17];
    const float* fc_W     = (const float*)d_in[18];
    const float* fc_b     = (const float*)d_in[19];
    const float* out_W    = (const float*)d_in[20];
    const float* out_b    = (const float*)d_in[21];
    float* out = (float*)d_out;

    float* d_xw1;   cudaGetSymbolAddress((void**)&d_xw1,   g_xw1);
    float* d_h1;    cudaGetSymbolAddress((void**)&d_h1,    g_h1);
    float* d_gout;  cudaGetSymbolAddress((void**)&d_gout,  g_out);
    float* d_cat;   cudaGetSymbolAddress((void**)&d_cat,   g_cat);
    float* d_fused; cudaGetSymbolAddress((void**)&d_fused, g_fused);

    // 1. transpose the four 768x256 recurrent matrices into float4-over-k layout
    k_prep<<<(4*64*G3 + 255)/256, 256>>>(r1_Whh0, r2_Whh0, r1_Whh1, r2_Whh1);
    // 2. layer-0 recurrence with fused input projection (both GRUs via grid.y)
    k_rec<1><<<dim3(BATCH/TB, 2), 512>>>((const float*)0, received,
                                         r1_Wih0, r2_Wih0, r1_bih0, r2_bih0,
                                         0, r1_bhh0, r2_bhh0, d_h1);
    // 3. layer-1 gate inputs: xw1 = h1 @ Wih1.T + bih1 (both GRUs via grid.z)
    k_gemm<<<dim3(G3/128, BL/128, 2), 256>>>(d_h1, (size_t)BL*HDIM,
                                             r1_Wih1, r2_Wih1, r1_bih1, r2_bih1,
                                             d_xw1, (size_t)BL*G3, G3, HDIM);
    // 4. layer-1 recurrence (pipelined xw)
    k_rec<0><<<dim3(BATCH/TB, 2), 512>>>(d_xw1, (const float*)0,
                                         (const float*)0, (const float*)0,
                                         (const float*)0, (const float*)0,
                                         2, r1_bhh1, r2_bhh1, d_gout);
    // 5. attention scalars q,e
    k_qe<<<dim3(BL/8, 2), 256>>>(attn_w);
    // 6. windowed softmax attention + concat
    k_attn<<<dim3(BM95, 2), 256>>>();
    // 7. FC over both branches stacked
    k_gemm<<<dim3(HDIM/128, (2*BM95)/128, 1), 256>>>(d_cat, 0,
                                                     fc_W, fc_W, fc_b, fc_b,
                                                     d_fused, 0, HDIM, 2*HDIM);
    // 8. final projection + sigmoid
    k_final<<<BL/8, 256>>>(out_W, out_b, out);
}

// round 6
// speedup vs baseline: 1.6870x; 1.0187x over previous
#include <cuda_runtime.h>
#include <math.h>

#define BATCH 512
#define LSEQ  100
#define NINPUT 3
#define HDIM  256
#define G3    768
#define DSH   10
#define WINW  5
#define MSEQ  95          // LSEQ - WINW
#define TB    8           // batch samples per recurrent block
#define NC    8           // kk slices cached in SMEM per k-half (16 total)

#define BL    (BATCH*LSEQ)      // 51200
#define BM95  (BATCH*MSEQ)      // 48640

typedef unsigned long long u64;

// ---------------- scratch (static device memory; no allocations) ----------
__device__ float  g_xw1 [2*BL*G3];          // layer-1 gate inputs, per GRU
__device__ float  g_h1  [2*BL*HDIM];        // layer-0 outputs
__device__ float  g_out [2*BL*HDIM];        // layer-1 outputs (out1/out2)
__device__ float  g_q   [2*BL];
__device__ float  g_e   [2*BL];
__device__ float  g_cat [2*BM95*2*HDIM];    // [c, out_shift] concat for FC
__device__ float  g_fused[2*BM95*HDIM];     // FC output
__device__ float4 g_wT4 [4*64*G3];          // transposed Whh, float4 over k
// wT4 slots: 0=r1_Whh0 1=r2_Whh0 2=r1_Whh1 3=r2_Whh1

__device__ __forceinline__ float sigf(float x) { return 1.f / (1.f + __expf(-x)); }

// packed dual-fp32 FMA: acc.{lo,hi} += a.{lo,hi} * b.{lo,hi}
__device__ __forceinline__ void fma2(u64& acc, u64 a, u64 b) {
    asm("fma.rn.f32x2 %0, %1, %2, %0;" : "+l"(acc) : "l"(a), "l"(b));
}
__device__ __forceinline__ u64 splat2(float x) {
    u64 r; asm("mov.b64 %0, {%1, %1};" : "=l"(r) : "f"(x)); return r;
}
__device__ __forceinline__ float sum2(u64 v) {
    float lo, hi; asm("mov.b64 {%0, %1}, %2;" : "=f"(lo), "=f"(hi) : "l"(v));
    return lo + hi;
}

// ---------------- weight transpose: W[g][k] -> wT4[k/4][g] ----------------
__global__ void k_prep(const float* __restrict__ w0, const float* __restrict__ w1,
                       const float* __restrict__ w2, const float* __restrict__ w3)
{
    int idx = blockIdx.x * blockDim.x + threadIdx.x;
    if (idx >= 4 * 64 * G3) return;
    int g  = idx % G3;
    int k4 = (idx / G3) % 64;
    int m  = idx / (G3 * 64);
    const float* W = (m == 0) ? w0 : (m == 1) ? w1 : (m == 2) ? w2 : w3;
    const float* p = W + g * HDIM + 4 * k4;
    g_wT4[idx] = make_float4(p[0], p[1], p[2], p[3]);
}

// ---------------- GRU recurrence ------------------------------------------
// 512 threads, k-split halves, SMEM weight cache (NC slices/half) +
// register-double-buffered gmem weight prefetch + pipelined gate inputs.
// FUSE=1: layer 0 — input projection (NINPUT=3) fused, weights in registers.
// FUSE=0: layer 1 — reads precomputed gate inputs xw_base (bias folded).
// Threads (kh, j): kh = tid>>8 selects k-half, j = tid&255 the gate column.
// Pointwise phase is split: half kh updates batch samples [4kh, 4kh+4).
template<int FUSE>
__global__ void __launch_bounds__(512, 1)
k_rec(const float* __restrict__ xw_base, const float* __restrict__ xin,
      const float* __restrict__ Wih_0, const float* __restrict__ Wih_1,
      const float* __restrict__ bih_0, const float* __restrict__ bih_1,
      int wslot,
      const float* __restrict__ bhh_0, const float* __restrict__ bhh_1,
      float* __restrict__ hout_base)
{
    int r  = blockIdx.y;
    int tid = threadIdx.x;
    int j  = tid & 255;                   // gate/hidden index 0..255
    int kh = tid >> 8;                    // k half: 0 or 1
    int b0 = blockIdx.x * TB;
    const float*  bhh  = r ? bhh_1 : bhh_0;
    const float4* Wbase = g_wT4 + (size_t)(wslot + r) * (64 * G3);
    const float4* W    = Wbase + kh * 32 * G3;       // this half's 32 slices
    const float4* Wg   = W + NC * G3;                // gmem part (slices NC..31)
    const float*  xw   = xw_base ? (xw_base + (size_t)r * BL * G3) : (const float*)0;
    float*        hout = hout_base + (size_t)r * BL * HDIM;

    // dynamic SMEM carve: hs | ps | Wc
    extern __shared__ __align__(16) char dsm[];
    float*  hs = (float*)dsm;                         // [TB][HDIM]
    float*  ps = hs + TB * HDIM;                      // [2][3][4][HDIM]
    float4* Wc = (float4*)(ps + 2 * 3 * 4 * HDIM);    // [2][NC][G3]
    const float4* Wch = Wc + kh * NC * G3;

    // one-time: stage the first NC weight slices of each half into SMEM
    for (int idx = tid; idx < 2 * NC * G3; idx += 512) {
        int half = idx / (NC * G3);
        int rem  = idx % (NC * G3);
        Wc[idx] = Wbase[half * 32 * G3 + rem];
    }

    int bown = kh * 4;                    // batch samples this half updates
    float* ps_w       = ps + kh * 3 * 4 * HDIM;
    const float* ps_r = ps + (1 - kh) * 3 * 4 * HDIM;

    // fused input-projection weights (layer 0)
    float wx[9], bx[3];
    if (FUSE) {
        const float* Wih = r ? Wih_1 : Wih_0;
        const float* bih = r ? bih_1 : bih_0;
#pragma unroll
        for (int g = 0; g < 3; g++) {
            wx[g*3+0] = Wih[(j + g*HDIM)*3 + 0];
            wx[g*3+1] = Wih[(j + g*HDIM)*3 + 1];
            wx[g*3+2] = Wih[(j + g*HDIM)*3 + 2];
            bx[g]     = bih[j + g*HDIM];
        }
    }

#pragma unroll
    for (int i = 0; i < 4; i++) hs[(bown + i) * HDIM + j] = 0.f;
    float bhr = bhh[j], bhz = bhh[j + HDIM], bhn = bhh[j + 2*HDIM];

    // prologue: pipeline registers hold this half's step-0 gate inputs
    float xg[12];
    if (FUSE) {
#pragma unroll
        for (int i = 0; i < 4; i++) {
            size_t base = ((size_t)(b0 + bown + i) * LSEQ + 0) * NINPUT;
            xg[i*3+0] = xin[base+0]; xg[i*3+1] = xin[base+1]; xg[i*3+2] = xin[base+2];
        }
    } else {
#pragma unroll
        for (int i = 0; i < 4; i++) {
            size_t base = ((size_t)(b0 + bown + i) * LSEQ + 0) * G3;
            xg[i*3+0] = xw[base + j];
            xg[i*3+1] = xw[base + HDIM + j];
            xg[i*3+2] = xw[base + 2*HDIM + j];
        }
    }
    __syncthreads();

    const float* hb_own = hs + bown * HDIM       + kh * 128;
    const float* hb_oth = hs + (4 - bown) * HDIM + kh * 128;

    for (int t = 0; t < LSEQ; t++) {
        u64 arO[4], azO[4], anO[4], arX[4], azX[4], anX[4];
#pragma unroll
        for (int i = 0; i < 4; i++) {
            arO[i]=0ull; azO[i]=0ull; anO[i]=0ull;
            arX[i]=0ull; azX[i]=0ull; anX[i]=0ull;
        }

        // ---- phase 1: SMEM-cached weight slices (kk 0..NC-1) ----
#pragma unroll
        for (int kk = 0; kk < NC; kk++) {
            ulonglong2 w0 = *(const ulonglong2*)&Wch[kk*G3 + j];
            ulonglong2 w1 = *(const ulonglong2*)&Wch[kk*G3 + HDIM + j];
            ulonglong2 w2 = *(const ulonglong2*)&Wch[kk*G3 + 2*HDIM + j];
#pragma unroll
            for (int i = 0; i < 4; i++) {
                ulonglong2 h2 = *(const ulonglong2*)&hb_own[i*HDIM + kk*4];
                fma2(arO[i], w0.x, h2.x); fma2(arO[i], w0.y, h2.y);
                fma2(azO[i], w1.x, h2.x); fma2(azO[i], w1.y, h2.y);
                fma2(anO[i], w2.x, h2.x); fma2(anO[i], w2.y, h2.y);
            }
#pragma unroll
            for (int i = 0; i < 4; i++) {
                ulonglong2 h2 = *(const ulonglong2*)&hb_oth[i*HDIM + kk*4];
                fma2(arX[i], w0.x, h2.x); fma2(arX[i], w0.y, h2.y);
                fma2(azX[i], w1.x, h2.x); fma2(azX[i], w1.y, h2.y);
                fma2(anX[i], w2.x, h2.x); fma2(anX[i], w2.y, h2.y);
            }
        }

        // ---- phase 2: gmem weight slices (kk NC..31), prefetch depth 2 ----
        {
            ulonglong2 p0[2], p1[2], p2[2];
#pragma unroll
            for (int d = 0; d < 2; d++) {
                p0[d] = *(const ulonglong2*)&Wg[d*G3 + j];
                p1[d] = *(const ulonglong2*)&Wg[d*G3 + HDIM + j];
                p2[d] = *(const ulonglong2*)&Wg[d*G3 + 2*HDIM + j];
            }
#pragma unroll
            for (int kk = NC; kk < 32; kk++) {
                int s = kk & 1;
                ulonglong2 w0 = p0[s], w1 = p1[s], w2 = p2[s];
                if (kk + 2 < 32) {
                    p0[s] = *(const ulonglong2*)&Wg[(kk+2-NC)*G3 + j];
                    p1[s] = *(const ulonglong2*)&Wg[(kk+2-NC)*G3 + HDIM + j];
                    p2[s] = *(const ulonglong2*)&Wg[(kk+2-NC)*G3 + 2*HDIM + j];
                }
#pragma unroll
                for (int i = 0; i < 4; i++) {
                    ulonglong2 h2 = *(const ulonglong2*)&hb_own[i*HDIM + kk*4];
                    fma2(arO[i], w0.x, h2.x); fma2(arO[i], w0.y, h2.y);
                    fma2(azO[i], w1.x, h2.x); fma2(azO[i], w1.y, h2.y);
                    fma2(anO[i], w2.x, h2.x); fma2(anO[i], w2.y, h2.y);
                }
#pragma unroll
                for (int i = 0; i < 4; i++) {
                    ulonglong2 h2 = *(const ulonglong2*)&hb_oth[i*HDIM + kk*4];
                    fma2(arX[i], w0.x, h2.x); fma2(arX[i], w0.y, h2.y);
                    fma2(azX[i], w1.x, h2.x); fma2(azX[i], w1.y, h2.y);
                    fma2(anX[i], w2.x, h2.x); fma2(anX[i], w2.y, h2.y);
                }
            }
        }

        // export partials for the OTHER half's samples
#pragma unroll
        for (int i = 0; i < 4; i++) {
            ps_w[0*4*HDIM + i*HDIM + j] = sum2(arX[i]);
            ps_w[1*4*HDIM + i*HDIM + j] = sum2(azX[i]);
            ps_w[2*4*HDIM + i*HDIM + j] = sum2(anX[i]);
        }
        __syncthreads();

        // pointwise update for this half's 4 samples
#pragma unroll
        for (int i = 0; i < 4; i++) {
            float gr, gz, gn;
            if (FUSE) {
                float x0 = xg[i*3+0], x1 = xg[i*3+1], x2 = xg[i*3+2];
                gr = bx[0] + x0*wx[0] + x1*wx[1] + x2*wx[2];
                gz = bx[1] + x0*wx[3] + x1*wx[4] + x2*wx[5];
                gn = bx[2] + x0*wx[6] + x1*wx[7] + x2*wx[8];
            } else {
                gr = xg[i*3+0]; gz = xg[i*3+1]; gn = xg[i*3+2];
            }
            float rg = sigf(gr + sum2(arO[i]) + ps_r[0*4*HDIM + i*HDIM + j] + bhr);
            float zg = sigf(gz + sum2(azO[i]) + ps_r[1*4*HDIM + i*HDIM + j] + bhz);
            float ng = tanhf(gn + rg * (sum2(anO[i]) + ps_r[2*4*HDIM + i*HDIM + j] + bhn));
            float hn = (1.f - zg) * ng + zg * hs[(bown + i)*HDIM + j];
            hs[(bown + i)*HDIM + j] = hn;
            hout[((size_t)(b0 + bown + i) * LSEQ + t) * HDIM + j] = hn;
        }
        // prefetch next step's gate inputs (consumed after next FMA phase)
        if (t + 1 < LSEQ) {
            if (FUSE) {
#pragma unroll
                for (int i = 0; i < 4; i++) {
                    size_t base = ((size_t)(b0 + bown + i) * LSEQ + (t+1)) * NINPUT;
                    xg[i*3+0] = xin[base+0]; xg[i*3+1] = xin[base+1]; xg[i*3+2] = xin[base+2];
                }
            } else {
#pragma unroll
                for (int i = 0; i < 4; i++) {
                    size_t base = ((size_t)(b0 + bown + i) * LSEQ + (t+1)) * G3;
                    xg[i*3+0] = xw[base + j];
                    xg[i*3+1] = xw[base + HDIM + j];
                    xg[i*3+2] = xw[base + 2*HDIM + j];
                }
            }
        }
        __syncthreads();
    }
}

#define REC_SMEM ((TB*HDIM + 2*3*4*HDIM) * 4 + 2*NC*G3*16)

// ---------------- SGEMM: C[M,N] = A[M,K] @ B[N,K].T + bias ----------------
// 128x128 block tile, 256 threads, 8x8 per thread (f32x2), double-buffered.
__global__ void __launch_bounds__(256, 2)
k_gemm(const float* __restrict__ A, size_t strideAz,
       const float* __restrict__ B0, const float* __restrict__ B1,
       const float* __restrict__ bias0, const float* __restrict__ bias1,
       float* __restrict__ C, size_t strideCz,
       int N, int K)
{
    int z = blockIdx.z;
    const float* Az   = A + (size_t)z * strideAz;
    const float* Bw   = z ? B1 : B0;
    const float* bias = z ? bias1 : bias0;
    float*       Cz   = C + (size_t)z * strideCz;

    __shared__ __align__(16) float As[2][8][128];
    __shared__ __align__(16) float Bs[2][8][128];

    int bm = blockIdx.y * 128;
    int bn = blockIdx.x * 128;
    int tid = threadIdx.x;

    int lrow = tid >> 1;
    int lk   = (tid & 1) * 4;
    int tm = (tid >> 4) * 8;
    int tn = (tid & 15) * 8;

    u64 acc[4][8];
#pragma unroll
    for (int p = 0; p < 4; p++)
#pragma unroll
        for (int n = 0; n < 8; n++) acc[p][n] = 0ull;

    const int KT = K >> 3;

    float4 a4 = *(const float4*)&Az[(size_t)(bm + lrow) * K + lk];
    float4 b4 = *(const float4*)&Bw[(size_t)(bn + lrow) * K + lk];
    As[0][lk+0][lrow] = a4.x; As[0][lk+1][lrow] = a4.y;
    As[0][lk+2][lrow] = a4.z; As[0][lk+3][lrow] = a4.w;
    Bs[0][lk+0][lrow] = b4.x; Bs[0][lk+1][lrow] = b4.y;
    Bs[0][lk+2][lrow] = b4.z; Bs[0][lk+3][lrow] = b4.w;
    __syncthreads();

    for (int kt = 0; kt < KT; kt++) {
        int cur = kt & 1;
        if (kt + 1 < KT) {
            int k0 = (kt + 1) * 8;
            a4 = *(const float4*)&Az[(size_t)(bm + lrow) * K + k0 + lk];
            b4 = *(const float4*)&Bw[(size_t)(bn + lrow) * K + k0 + lk];
        }
#pragma unroll
        for (int k = 0; k < 8; k++) {
            ulonglong2 a01 = *(const ulonglong2*)&As[cur][k][tm];
            ulonglong2 a23 = *(const ulonglong2*)&As[cur][k][tm+4];
            float4 bv0 = *(const float4*)&Bs[cur][k][tn];
            float4 bv1 = *(const float4*)&Bs[cur][k][tn+4];
            u64 ap[4] = { a01.x, a01.y, a23.x, a23.y };
            u64 bs[8] = { splat2(bv0.x), splat2(bv0.y), splat2(bv0.z), splat2(bv0.w),
                          splat2(bv1.x), splat2(bv1.y), splat2(bv1.z), splat2(bv1.w) };
#pragma unroll
            for (int p = 0; p < 4; p++)
#pragma unroll
                for (int n = 0; n < 8; n++)
                    fma2(acc[p][n], ap[p], bs[n]);
        }
        if (kt + 1 < KT) {
            int nxt = cur ^ 1;
            As[nxt][lk+0][lrow] = a4.x; As[nxt][lk+1][lrow] = a4.y;
            As[nxt][lk+2][lrow] = a4.z; As[nxt][lk+3][lrow] = a4.w;
            Bs[nxt][lk+0][lrow] = b4.x; Bs[nxt][lk+1][lrow] = b4.y;
            Bs[nxt][lk+2][lrow] = b4.z; Bs[nxt][lk+3][lrow] = b4.w;
        }
        __syncthreads();
    }

    float bv[8];
#pragma unroll
    for (int n = 0; n < 8; n++) bv[n] = bias[bn + tn + n];
#pragma unroll
    for (int p = 0; p < 4; p++) {
        float r0[8], r1[8];
#pragma unroll
        for (int n = 0; n < 8; n++) {
            float lo, hi;
            asm("mov.b64 {%0, %1}, %2;" : "=f"(lo), "=f"(hi) : "l"(acc[p][n]));
            r0[n] = lo + bv[n]; r1[n] = hi + bv[n];
        }
        size_t row0 = (size_t)(bm + tm + 2*p) * N + bn + tn;
        size_t row1 = row0 + N;
        *(float4*)&Cz[row0]     = make_float4(r0[0], r0[1], r0[2], r0[3]);
        *(float4*)&Cz[row0 + 4] = make_float4(r0[4], r0[5], r0[6], r0[7]);
        *(float4*)&Cz[row1]     = make_float4(r1[0], r1[1], r1[2], r1[3]);
        *(float4*)&Cz[row1 + 4] = make_float4(r1[4], r1[5], r1[6], r1[7]);
    }
}

// ---------------- q = out@aw[:H], e = out@aw[H:] (warp per (b,l)) ----------
__global__ void k_qe(const float* __restrict__ attn_w)
{
    int r    = blockIdx.y;
    int w    = blockIdx.x * 8 + (threadIdx.x >> 5);
    int lane = threadIdx.x & 31;
    const float* o = g_out + ((size_t)r * BL + w) * HDIM;
    float q = 0.f, e = 0.f;
#pragma unroll
    for (int h = lane * 8; h < lane * 8 + 8; h += 4) {
        float4 ov = *(const float4*)&o[h];
        float4 a1 = *(const float4*)&attn_w[h];
        float4 a2 = *(const float4*)&attn_w[HDIM + h];
        q += ov.x*a1.x + ov.y*a1.y + ov.z*a1.z + ov.w*a1.w;
        e += ov.x*a2.x + ov.y*a2.y + ov.z*a2.z + ov.w*a2.w;
    }
#pragma unroll
    for (int off = 16; off; off >>= 1) {
        q += __shfl_down_sync(0xffffffffu, q, off);
        e += __shfl_down_sync(0xffffffffu, e, off);
    }
    if (lane == 0) { g_q[r * BL + w] = q; g_e[r * BL + w] = e; }
}

// ---------------- windowed attention + concat for FC ----------------------
__global__ void k_attn()
{
    int r    = blockIdx.y;
    int bl95 = blockIdx.x;
    int b    = bl95 / MSEQ, l = bl95 % MSEQ;
    int h    = threadIdx.x;

    const float* qrow = g_q + r * BL + b * LSEQ;
    const float* erow = g_e + r * BL + b * LSEQ;
    float qv = qrow[l + WINW];
    float s[WINW];
    float mx = -1e30f;
#pragma unroll
    for (int k = 0; k < WINW; k++) { s[k] = qv + erow[l + k]; mx = fmaxf(mx, s[k]); }
    float sum = 0.f;
#pragma unroll
    for (int k = 0; k < WINW; k++) { s[k] = __expf(s[k] - mx); sum += s[k]; }
    float inv = 1.f / sum;

    const float* o = g_out + ((size_t)r * BL + b * LSEQ + l) * HDIM;
    float c = 0.f;
#pragma unroll
    for (int k = 0; k < WINW; k++) c += s[k] * inv * o[k * HDIM + h];

    size_t m = (size_t)r * BM95 + bl95;
    g_cat[m * (2*HDIM) + h]        = c;
    g_cat[m * (2*HDIM) + HDIM + h] = o[WINW * HDIM + h];
}

// ---------------- final head: concat(rnn1[b,l], rnn2[b,min(l+D,99)]) ------
__global__ void k_final(const float* __restrict__ outW, const float* __restrict__ outb,
                        float* __restrict__ out)
{
    int w    = blockIdx.x * 8 + (threadIdx.x >> 5);
    int lane = threadIdx.x & 31;
    int b = w / LSEQ, l = w % LSEQ;

    const float* A1 = (l < WINW)
        ? (g_out   + ((size_t)(b * LSEQ + l)) * HDIM)
        : (g_fused + ((size_t)(b * MSEQ + l - WINW)) * HDIM);
    int lidx = min(l + DSH, LSEQ - 1);
    const float* A2 = (lidx < WINW)
        ? (g_out   + ((size_t)BL + b * LSEQ + lidx) * HDIM)
        : (g_fused + ((size_t)BM95 + b * MSEQ + lidx - WINW) * HDIM);

    float acc = 0.f;
#pragma unroll
    for (int h = lane * 8; h < lane * 8 + 8; h += 4) {
        float4 a  = *(const float4*)&A1[h];
        float4 w1 = *(const float4*)&outW[h];
        acc += a.x*w1.x + a.y*w1.y + a.z*w1.z + a.w*w1.w;
        float4 a2 = *(const float4*)&A2[h];
        float4 w2 = *(const float4*)&outW[HDIM + h];
        acc += a2.x*w2.x + a2.y*w2.y + a2.z*w2.z + a2.w*w2.w;
    }
#pragma unroll
    for (int off = 16; off; off >>= 1)
        acc += __shfl_down_sync(0xffffffffu, acc, off);
    if (lane == 0) out[w] = 1.f / (1.f + __expf(-(acc + outb[0])));
}

// ---------------------------------------------------------------------------
extern "C" void kernel_launch(void* const* d_in, const int* in_sizes, int n_in,
                              void* d_out, int out_size)
{
    const float* received = (const float*)d_in[0];
    const float* r1_Wih0  = (const float*)d_in[1];
    const float* r1_Whh0  = (const float*)d_in[2];
    const float* r1_bih0  = (const float*)d_in[3];
    const float* r1_bhh0  = (const float*)d_in[4];
    const float* r1_Wih1  = (const float*)d_in[5];
    const float* r1_Whh1  = (const float*)d_in[6];
    const float* r1_bih1  = (const float*)d_in[7];
    const float* r1_bhh1  = (const float*)d_in[8];
    const float* r2_Wih0  = (const float*)d_in[9];
    const float* r2_Whh0  = (const float*)d_in[10];
    const float* r2_bih0  = (const float*)d_in[11];
    const float* r2_bhh0  = (const float*)d_in[12];
    const float* r2_Wih1  = (const float*)d_in[13];
    const float* r2_Whh1  = (const float*)d_in[14];
    const float* r2_bih1  = (const float*)d_in[15];
    const float* r2_bhh1  = (const float*)d_in[16];
    const float* attn_w   = (const float*)d_in[17];
    const float* fc_W     = (const float*)d_in[18];
    const float* fc_b     = (const float*)d_in[19];
    const float* out_W    = (const float*)d_in[20];
    const float* out_b    = (const float*)d_in[21];
    float* out = (float*)d_out;

    float* d_xw1;   cudaGetSymbolAddress((void**)&d_xw1,   g_xw1);
    float* d_h1;    cudaGetSymbolAddress((void**)&d_h1,    g_h1);
    float* d_gout;  cudaGetSymbolAddress((void**)&d_gout,  g_out);
    float* d_cat;   cudaGetSymbolAddress((void**)&d_cat,   g_cat);
    float* d_fused; cudaGetSymbolAddress((void**)&d_fused, g_fused);

    static int smem_set = 0;
    if (!smem_set) {
        cudaFuncSetAttribute(k_rec<1>, cudaFuncAttributeMaxDynamicSharedMemorySize, REC_SMEM);
        cudaFuncSetAttribute(k_rec<0>, cudaFuncAttributeMaxDynamicSharedMemorySize, REC_SMEM);
        smem_set = 1;
    }

    // 1. transpose the four 768x256 recurrent matrices into float4-over-k layout
    k_prep<<<(4*64*G3 + 255)/256, 256>>>(r1_Whh0, r2_Whh0, r1_Whh1, r2_Whh1);
    // 2. layer-0 recurrence with fused input projection (both GRUs via grid.y)
    k_rec<1><<<dim3(BATCH/TB, 2), 512, REC_SMEM>>>((const float*)0, received,
                                         r1_Wih0, r2_Wih0, r1_bih0, r2_bih0,
                                         0, r1_bhh0, r2_bhh0, d_h1);
    // 3. layer-1 gate inputs: xw1 = h1 @ Wih1.T + bih1 (both GRUs via grid.z)
    k_gemm<<<dim3(G3/128, BL/128, 2), 256>>>(d_h1, (size_t)BL*HDIM,
                                             r1_Wih1, r2_Wih1, r1_bih1, r2_bih1,
                                             d_xw1, (size_t)BL*G3, G3, HDIM);
    // 4. layer-1 recurrence (pipelined xw)
    k_rec<0><<<dim3(BATCH/TB, 2), 512, REC_SMEM>>>(d_xw1, (const float*)0,
                                         (const float*)0, (const float*)0,
                                         (const float*)0, (const float*)0,
                                         2, r1_bhh1, r2_bhh1, d_gout);
    // 5. attention scalars q,e
    k_qe<<<dim3(BL/8, 2), 256>>>(attn_w);
    // 6. windowed softmax attention + concat
    k_attn<<<dim3(BM95, 2), 256>>>();
    // 7. FC over both branches stacked
    k_gemm<<<dim3(HDIM/128, (2*BM95)/128, 1), 256>>>(d_cat, 0,
                                                     fc_W, fc_W, fc_b, fc_b,
                                                     d_fused, 0, HDIM, 2*HDIM);
    // 8. final projection + sigmoid
    k_final<<<BL/8, 256>>>(out_W, out_b, out);
}